// round 3
// baseline (speedup 1.0000x reference)
#include <cuda_runtime.h>
#include <math.h>
#include <stdint.h>

#define N_ 8192
#define E_ 131072
#define M_ (E_ + N_)          // 139264 edges incl self loops
#define H_ 128
#define K_ 4096

// P rows in smem: two halves, each float4 per k. lo[4k+r] r=0..3, hi[4K+4k+r] r=4..7.
// Injective by construction; 16B chunk position = k mod 8 (uniform for random k).
#define PSH_WORDS (8*K_)

// ---------------- device scratch ----------------
static __device__ float g_bufA[(size_t)N_*H_];
static __device__ float g_bufB[(size_t)N_*H_];
static __device__ float g_bufC[(size_t)N_*H_];
static __device__ float g_bufT[(size_t)N_*H_];
static __device__ float g_dis[N_];
static __device__ int   g_cnt[N_];
static __device__ int   g_fill[N_];
static __device__ int   g_rowptr[N_+1];
static __device__ int   g_eidx[M_];
static __device__ float g_alpha[M_];
static __device__ float g_aq[N_];
static __device__ float g_ah[N_];
static __device__ float g_cl1[N_], g_cl2[N_], g_cl3[N_];
static __device__ float g_fit[N_];
static __device__ int   g_sel[N_];
static __device__ int   g_col[N_];
static __device__ int   g_ncol[K_];
static __device__ float g_xp[(size_t)K_*H_];
static __device__ int   g_scnt[N_];
static __device__ int   g_srowptr[N_+1];
static __device__ int2  g_sp[M_];            // packed (col k, alpha bits)
static __device__ float g_Ac[(size_t)K_*K_];

// ---------------- helpers ----------------
__device__ __forceinline__ int esrc_f(const int* __restrict__ e0, int e){ return (e < E_) ? e0[e] : (e - E_); }
__device__ __forceinline__ int edst_f(const int* __restrict__ e1, int e){ return (e < E_) ? e1[e] : (e - E_); }

// ---------------- small utility kernels ----------------
__global__ void k_init0(){
    int i = blockIdx.x*blockDim.x + threadIdx.x;
    if (i < N_){ g_cnt[i]=0; g_fill[i]=0; g_scnt[i]=0; }
}
__global__ void k_zero_fill(){
    int i = blockIdx.x*blockDim.x + threadIdx.x;
    if (i < N_) g_fill[i]=0;
}
__global__ void k_zeroAc(){
    size_t i = (size_t)blockIdx.x*blockDim.x + threadIdx.x;
    size_t st = (size_t)gridDim.x*blockDim.x;
    float4* p = (float4*)g_Ac;
    size_t n = (size_t)K_*K_/4;
    float4 z = make_float4(0.f,0.f,0.f,0.f);
    for(; i<n; i+=st) p[i]=z;
}
__global__ void k_count(const int* __restrict__ e1){
    int e = blockIdx.x*blockDim.x + threadIdx.x;
    if (e < M_) atomicAdd(&g_cnt[edst_f(e1,e)], 1);
}
__global__ void k_dis(){
    int i = blockIdx.x*blockDim.x + threadIdx.x;
    if (i < N_) g_dis[i] = rsqrtf((float)g_cnt[i]);
}
// exclusive scan of exactly 8192 ints with 1024 threads (shfl-based)
__global__ void k_scan8192(const int* __restrict__ in, int* __restrict__ out){
    __shared__ int wsum[32];
    int tid=threadIdx.x, lane=tid&31, wid=tid>>5;
    int4 a=((const int4*)in)[tid*2], b=((const int4*)in)[tid*2+1];
    int l[8]={a.x,a.y,a.z,a.w,b.x,b.y,b.z,b.w};
    int s=0;
    #pragma unroll
    for(int q=0;q<8;q++) s+=l[q];
    int inc=s;
    #pragma unroll
    for(int o=1;o<32;o<<=1){ int t=__shfl_up_sync(0xffffffffu,inc,o); if(lane>=o) inc+=t; }
    if(lane==31) wsum[wid]=inc;
    __syncthreads();
    if (wid==0){
        int v = wsum[lane];
        #pragma unroll
        for(int o=1;o<32;o<<=1){ int t=__shfl_up_sync(0xffffffffu,v,o); if(lane>=o) v+=t; }
        wsum[lane]=v;
    }
    __syncthreads();
    int r = inc - s + (wid? wsum[wid-1]:0);
    int4 o1,o2;
    o1.x=r; r+=l[0]; o1.y=r; r+=l[1]; o1.z=r; r+=l[2]; o1.w=r; r+=l[3];
    o2.x=r; r+=l[4]; o2.y=r; r+=l[5]; o2.z=r; r+=l[6]; o2.w=r; r+=l[7];
    ((int4*)out)[tid*2]=o1; ((int4*)out)[tid*2+1]=o2;
    if (tid==1023) out[8192]=r;
}
__global__ void k_fill(const int* __restrict__ e1){
    int e = blockIdx.x*blockDim.x + threadIdx.x;
    if (e < M_){
        int d = edst_f(e1,e);
        int pos = g_rowptr[d] + atomicAdd(&g_fill[d],1);
        g_eidx[pos]=e;
    }
}

// ---------------- 8192x128 @ 128x128 GEMM ----------------
__global__ void k_gemm(const float* __restrict__ x, const float* __restrict__ w, float* __restrict__ y){
    __shared__ __align__(16) float xs[128*64];   // [kk][r]
    int r0 = blockIdx.x*64;
    int tid = threadIdx.x;
    for (int idx=tid; idx<64*128; idx+=256){
        int r = idx >> 7;
        int kk = idx & 127;
        xs[kk*64 + r] = x[(size_t)(r0+r)*128 + kk];
    }
    __syncthreads();
    int cg = tid & 31;
    int rg = tid >> 5;
    float acc[8][4];
    #pragma unroll
    for(int r=0;r<8;r++){ acc[r][0]=0.f;acc[r][1]=0.f;acc[r][2]=0.f;acc[r][3]=0.f; }
    #pragma unroll 4
    for(int kk=0;kk<128;kk++){
        float4 wv = *(const float4*)(w + kk*128 + cg*4);
        float4 x0 = *(const float4*)(xs + kk*64 + rg*8);
        float4 x1 = *(const float4*)(xs + kk*64 + rg*8 + 4);
        float xv[8] = {x0.x,x0.y,x0.z,x0.w,x1.x,x1.y,x1.z,x1.w};
        #pragma unroll
        for(int r=0;r<8;r++){
            acc[r][0] += xv[r]*wv.x; acc[r][1] += xv[r]*wv.y;
            acc[r][2] += xv[r]*wv.z; acc[r][3] += xv[r]*wv.w;
        }
    }
    #pragma unroll
    for(int r=0;r<8;r++){
        float4 o = make_float4(acc[r][0],acc[r][1],acc[r][2],acc[r][3]);
        *(float4*)(y + (size_t)(r0+rg*8+r)*128 + cg*4) = o;
    }
}

// ---------------- GCN aggregation ----------------
__global__ void k_aggr(const float* __restrict__ y, const float* __restrict__ b,
                       float* __restrict__ out, const int* __restrict__ e0, int dotanh){
    int d = blockIdx.x, t = threadIdx.x;
    int beg = g_rowptr[d], end = g_rowptr[d+1];
    float dd = g_dis[d], acc = 0.f;
    for (int s=beg; s<end; s++){
        int e = g_eidx[s];
        int sr = esrc_f(e0,e);
        acc += y[(size_t)sr*128 + t] * (g_dis[sr]*dd);
    }
    acc += b[t];
    if (dotanh) acc = tanhf(acc);
    out[(size_t)d*128 + t] = acc;
}

__global__ void k_segmax(const float* __restrict__ h, float* __restrict__ out, const int* __restrict__ e0){
    int d = blockIdx.x, t = threadIdx.x;
    int beg = g_rowptr[d], end = g_rowptr[d+1];
    float acc = -INFINITY;
    for (int s=beg;s<end;s++){
        int sr = esrc_f(e0, g_eidx[s]);
        acc = fmaxf(acc, h[(size_t)sr*128 + t]);
    }
    out[(size_t)d*128 + t] = acc;
}

__global__ void k_dots(const float* __restrict__ xq, const float* __restrict__ h,
                       const float* __restrict__ att, const float* __restrict__ bq){
    int node = blockIdx.x*8 + (threadIdx.x>>5);
    int lane = threadIdx.x & 31;
    float s1=0.f, s2=0.f;
    for (int q=lane; q<128; q+=32){
        s1 += att[q]     * (xq[(size_t)node*128+q] + bq[q]);
        s2 += att[128+q] *  h[(size_t)node*128+q];
    }
    #pragma unroll
    for (int o=16;o;o>>=1){ s1 += __shfl_down_sync(0xffffffffu,s1,o); s2 += __shfl_down_sync(0xffffffffu,s2,o); }
    if (!lane){ g_aq[node]=s1; g_ah[node]=s2; }
}

__global__ void k_softcx(const float* __restrict__ h, float* __restrict__ cx, const int* __restrict__ e0){
    __shared__ float red[128];
    __shared__ float cache[1024];
    int d = blockIdx.x, t = threadIdx.x;
    int beg = g_rowptr[d], end = g_rowptr[d+1];
    float aqd = g_aq[d];
    float mx = -INFINITY;
    for (int s=beg+t; s<end; s+=128){
        int e = g_eidx[s];
        float sc = aqd + g_ah[esrc_f(e0,e)];
        sc = sc > 0.f ? sc : 0.2f*sc;
        if (s-beg < 1024) cache[s-beg] = sc;
        mx = fmaxf(mx, sc);
    }
    red[t]=mx; __syncthreads();
    for (int o=64;o;o>>=1){ if(t<o) red[t]=fmaxf(red[t],red[t+o]); __syncthreads(); }
    mx = red[0]; __syncthreads();
    float sm = 0.f;
    for (int s=beg+t; s<end; s+=128){
        float sc;
        if (s-beg < 1024) sc = cache[s-beg];
        else { int e=g_eidx[s]; sc = aqd + g_ah[esrc_f(e0,e)]; sc = sc>0.f? sc : 0.2f*sc; }
        float ee = __expf(sc - mx);
        if (s-beg < 1024) cache[s-beg] = ee;
        sm += ee;
    }
    red[t]=sm; __syncthreads();
    for (int o=64;o;o>>=1){ if(t<o) red[t]+=red[t+o]; __syncthreads(); }
    float inv = 1.f/red[0];
    for (int s=beg+t; s<end; s+=128){
        int e = g_eidx[s];
        float ee;
        if (s-beg < 1024) ee = cache[s-beg];
        else { float sc = aqd + g_ah[esrc_f(e0,e)]; sc = sc>0.f? sc:0.2f*sc; ee = __expf(sc-mx); }
        float a = ee*inv;
        g_alpha[e] = a;
        if (s-beg < 1024) cache[s-beg] = a;
    }
    __syncthreads();
    float acc = 0.f;
    for (int s=beg; s<end; s++){
        int e = g_eidx[s];
        float a = (s-beg < 1024) ? cache[s-beg] : g_alpha[e];
        acc += a * h[(size_t)esrc_f(e0,e)*128 + t];
    }
    cx[(size_t)d*128 + t] = acc;
}

__global__ void k_le(const float* __restrict__ cx, const float* __restrict__ lw1,
                     const float* __restrict__ lw2, const float* __restrict__ lw3){
    int node = blockIdx.x*8 + (threadIdx.x>>5);
    int lane = threadIdx.x & 31;
    float s1=0.f,s2=0.f,s3=0.f;
    for (int q=lane;q<128;q+=32){
        float v = cx[(size_t)node*128+q];
        s1 += v*lw1[q]; s2 += v*lw2[q]; s3 += v*lw3[q];
    }
    #pragma unroll
    for (int o=16;o;o>>=1){
        s1 += __shfl_down_sync(0xffffffffu,s1,o);
        s2 += __shfl_down_sync(0xffffffffu,s2,o);
        s3 += __shfl_down_sync(0xffffffffu,s3,o);
    }
    if (!lane){ g_cl1[node]=s1; g_cl2[node]=s2; g_cl3[node]=s3; }
}
__global__ void k_fit(const float* __restrict__ lb1, const int* __restrict__ e0){
    int d = blockIdx.x*blockDim.x + threadIdx.x;
    if (d >= N_) return;
    int beg=g_rowptr[d], end=g_rowptr[d+1];
    float s = 0.f;
    for (int q=beg;q<end;q++) s += g_cl3[esrc_f(e0, g_eidx[q])];
    float aggr = (float)(end-beg)*g_cl2[d] - s;
    float z = g_cl1[d] + lb1[0] + aggr;
    g_fit[d] = 1.f/(1.f + __expf(-z));
}

// ---------------- top-K via 4x8-bit histogram radix select (256 threads) ----------------
__global__ void k_topk(){
    __shared__ int hist[256];
    __shared__ int wred[8];
    __shared__ unsigned s_pref;
    __shared__ int s_need;
    int tid=threadIdx.x, lane=tid&31, wid=tid>>5;
    if (tid==0){ s_pref=0u; s_need=K_; }
    unsigned keys[32];
    #pragma unroll
    for (int q=0;q<32;q++){
        unsigned u=__float_as_uint(g_fit[tid*32+q]);
        keys[q] = (u & 0x80000000u) ? ~u : (u | 0x80000000u);
    }
    __syncthreads();
    for (int round=0; round<4; round++){
        int shift = 24 - 8*round;
        hist[tid]=0;
        __syncthreads();
        unsigned pref = s_pref;
        #pragma unroll
        for (int q=0;q<32;q++){
            unsigned k = keys[q];
            bool match = (round==0) || ((k >> (shift+8)) == (pref >> (shift+8)));
            if (match) atomicAdd(&hist[(k>>shift)&0xFFu], 1);
        }
        __syncthreads();
        int mine = hist[255-tid];
        int v = mine;
        #pragma unroll
        for (int o=1;o<32;o<<=1){ int t2=__shfl_up_sync(0xffffffffu,v,o); if(lane>=o) v+=t2; }
        if (lane==31) wred[wid]=v;
        __syncthreads();
        int woff=0;
        #pragma unroll
        for (int w=0;w<8;w++) if (w<wid) woff+=wred[w];
        v += woff;                  // inclusive count of keys in bins >= (255-tid)
        int need0 = s_need;
        int vex = v - mine;
        if (v >= need0 && vex < need0){
            s_pref = s_pref | ((unsigned)(255-tid) << shift);
            s_need = need0 - vex;
        }
        __syncthreads();
    }
    unsigned thr = s_pref;
    int need = s_need;
    int tcnt=0;
    #pragma unroll
    for (int q=0;q<32;q++) tcnt += (keys[q]==thr);
    int v=tcnt;
    #pragma unroll
    for (int o=1;o<32;o<<=1){ int t2=__shfl_up_sync(0xffffffffu,v,o); if(lane>=o) v+=t2; }
    if (lane==31) wred[wid]=v;
    __syncthreads();
    int woff=0;
    #pragma unroll
    for (int w=0;w<8;w++) if (w<wid) woff+=wred[w];
    int rank = v - tcnt + woff;
    int scnt=0;
    int selq[32];
    #pragma unroll
    for (int q=0;q<32;q++){
        unsigned k=keys[q];
        bool eq = (k==thr);
        int s = (k>thr) || (eq && rank < need);
        if (eq) rank++;
        selq[q]=s;
        g_sel[tid*32+q]=s;
        scnt+=s;
    }
    __syncthreads();
    v=scnt;
    #pragma unroll
    for (int o=1;o<32;o<<=1){ int t2=__shfl_up_sync(0xffffffffu,v,o); if(lane>=o) v+=t2; }
    if (lane==31) wred[wid]=v;
    __syncthreads();
    woff=0;
    #pragma unroll
    for (int w=0;w<8;w++) if (w<wid) woff+=wred[w];
    int base = v - scnt + woff;
    #pragma unroll
    for (int q=0;q<32;q++){
        int i = tid*32+q;
        if (selq[q]){ g_col[i]=base; g_ncol[base]=i; base++; }
        else g_col[i]=-1;
    }
}

__global__ void k_xp(const float* __restrict__ cx){
    int i = blockIdx.x, t = threadIdx.x;
    if (!g_sel[i]) return;
    g_xp[(size_t)g_col[i]*128 + t] = cx[(size_t)i*128 + t] * g_fit[i];
}

// ---------------- S CSR (by source) with packed entries ----------------
__global__ void k_scount(const int* __restrict__ e0, const int* __restrict__ e1){
    int e = blockIdx.x*blockDim.x + threadIdx.x;
    if (e < M_){
        int d = edst_f(e1,e);
        if (g_sel[d]) atomicAdd(&g_scnt[esrc_f(e0,e)], 1);
    }
}
__global__ void k_sfill(const int* __restrict__ e0, const int* __restrict__ e1){
    int e = blockIdx.x*blockDim.x + threadIdx.x;
    if (e < M_){
        int d = edst_f(e1,e);
        if (g_sel[d]){
            int s = esrc_f(e0,e);
            int pos = g_srowptr[s] + atomicAdd(&g_fill[s],1);
            g_sp[pos] = make_int2(g_col[d], __float_as_int(g_alpha[e]));
        }
    }
}

// ---------------- Ac scatter: warp per edge, Ac += S_s^T (outer) S_j ----------------
__global__ void k_AcScat(const int* __restrict__ e0, const int* __restrict__ e1){
    int gw = (blockIdx.x*blockDim.x + threadIdx.x) >> 5;
    int lane = threadIdx.x & 31;
    if (gw >= M_) return;
    int s = esrc_f(e0,gw), j = edst_f(e1,gw);
    int sb=g_srowptr[s], se=g_srowptr[s+1];
    int jb=g_srowptr[j], je=g_srowptr[j+1];
    if (sb==se || jb==je) return;
    int   m0=-1, m1=-1; float a0=0.f, a1=0.f;
    int q = jb + lane;
    if (q < je){ int2 p=g_sp[q]; m0=p.x; a0=__int_as_float(p.y); }
    q = jb + 32 + lane;
    if (q < je){ int2 p=g_sp[q]; m1=p.x; a1=__int_as_float(p.y); }
    for (int p=sb; p<se; p++){
        int2 kp = g_sp[p];
        float ak = __int_as_float(kp.y);
        size_t rb = (size_t)kp.x * K_;
        if (m0>=0) atomicAdd(&g_Ac[rb+m0], ak*a0);
        if (m1>=0) atomicAdd(&g_Ac[rb+m1], ak*a1);
        for (int qq=jb+64+lane; qq<je; qq+=32){
            int2 pe = g_sp[qq];
            atomicAdd(&g_Ac[rb+pe.x], ak*__int_as_float(pe.y));
        }
    }
}

// ---------------- fused: build 8 P-rows (registers->smem), then adj = P S^T ----------------
__global__ void k_adjF(float* __restrict__ adj){
    extern __shared__ __align__(16) float Psh[];   // lo[4k + r<4], hi[4K + 4k + (r-4)]
    int i0 = blockIdx.x*8, tid = threadIdx.x;
    #pragma unroll 1
    for (int r=0;r<8;r++){
        float acc[16];
        #pragma unroll
        for (int c=0;c<16;c++) acc[c]=0.f;
        int qb=g_srowptr[i0+r], qe=g_srowptr[i0+r+1];
        for (int q=qb;q<qe;q++){
            int2 kp = g_sp[q];
            float a = __int_as_float(kp.y);
            const float* row = &g_Ac[(size_t)kp.x*K_] + tid;
            #pragma unroll
            for (int c=0;c<16;c++) acc[c] += a*row[c*256];
        }
        float* half = Psh + ((r>=4) ? 4*K_ : 0);
        int rr = r & 3;
        #pragma unroll
        for (int c=0;c<16;c++){
            int k = tid + c*256;
            half[4*k + rr] = acc[c];
        }
    }
    __syncthreads();
    for (int j=tid; j<N_; j+=256){
        float b0=0,b1=0,b2=0,b3=0,b4=0,b5=0,b6=0,b7=0;
        int qb = g_srowptr[j], qe = g_srowptr[j+1];
        for (int q=qb;q<qe;q++){
            int2 kp = g_sp[q];
            float a = __int_as_float(kp.y);
            float4 p0 = *(const float4*)&Psh[4*kp.x];
            float4 p1 = *(const float4*)&Psh[4*K_ + 4*kp.x];
            b0 += a*p0.x; b1 += a*p0.y; b2 += a*p0.z; b3 += a*p0.w;
            b4 += a*p1.x; b5 += a*p1.y; b6 += a*p1.z; b7 += a*p1.w;
        }
        adj[(size_t)(i0+0)*N_ + j]=b0; adj[(size_t)(i0+1)*N_ + j]=b1;
        adj[(size_t)(i0+2)*N_ + j]=b2; adj[(size_t)(i0+3)*N_ + j]=b3;
        adj[(size_t)(i0+4)*N_ + j]=b4; adj[(size_t)(i0+5)*N_ + j]=b5;
        adj[(size_t)(i0+6)*N_ + j]=b6; adj[(size_t)(i0+7)*N_ + j]=b7;
    }
}

// x_out[i,:] = sum over S row i: alpha*xp[k,:]
__global__ void k_xout(float* __restrict__ out){
    int i = blockIdx.x, t = threadIdx.x;
    float acc = 0.f;
    for (int q=g_srowptr[i]; q<g_srowptr[i+1]; q++){
        int2 kp = g_sp[q];
        acc += __int_as_float(kp.y) * g_xp[(size_t)kp.x*128 + t];
    }
    out[(size_t)i*128 + t] = acc;
}

// ---------------- host ----------------
extern "C" void kernel_launch(void* const* d_in, const int* in_sizes, int n_in,
                              void* d_out, int out_size){
    const float* nodes = (const float*)d_in[0];
    const int*   edges = (const int*)d_in[1];
    const int* e0 = edges;
    const int* e1 = edges + E_;
    const float* w1 = (const float*)d_in[3];  const float* b1 = (const float*)d_in[4];
    const float* w2 = (const float*)d_in[5];  const float* b2 = (const float*)d_in[6];
    const float* w3 = (const float*)d_in[7];  const float* b3 = (const float*)d_in[8];
    const float* w4 = (const float*)d_in[9];  const float* b4 = (const float*)d_in[10];
    const float* w5 = (const float*)d_in[11]; const float* b5 = (const float*)d_in[12];
    const float* wq = (const float*)d_in[13]; const float* bq = (const float*)d_in[14];
    const float* att = (const float*)d_in[15];
    const float* lw1 = (const float*)d_in[16]; const float* lb1 = (const float*)d_in[17];
    const float* lw2 = (const float*)d_in[18]; const float* lw3 = (const float*)d_in[19];

    float* out = (float*)d_out;
    float* x2out = out;
    float* adj  = out + (size_t)N_*H_;

    float *A,*B,*C,*T; int *cnt,*rowptr,*scnt,*srowptr;
    cudaGetSymbolAddress((void**)&A, g_bufA);
    cudaGetSymbolAddress((void**)&B, g_bufB);
    cudaGetSymbolAddress((void**)&C, g_bufC);
    cudaGetSymbolAddress((void**)&T, g_bufT);
    cudaGetSymbolAddress((void**)&cnt, g_cnt);
    cudaGetSymbolAddress((void**)&rowptr, g_rowptr);
    cudaGetSymbolAddress((void**)&scnt, g_scnt);
    cudaGetSymbolAddress((void**)&srowptr, g_srowptr);

    const int TB = 256;
    const int MB = (M_ + TB - 1)/TB;

    // graph prep (+ zero Ac early)
    k_init0<<<(N_+TB-1)/TB, TB>>>();
    k_zeroAc<<<2048, 256>>>();
    k_count<<<MB, TB>>>(e1);
    k_dis<<<(N_+TB-1)/TB, TB>>>();
    k_scan8192<<<1,1024>>>(cnt, rowptr);
    k_fill<<<MB, TB>>>(e1);

    // encoder
    k_gemm<<<128,256>>>(nodes, w1, T);
    k_aggr<<<N_,128>>>(T, b1, A, e0, 1);
    k_gemm<<<128,256>>>(A, w2, T);
    k_aggr<<<N_,128>>>(T, b2, B, e0, 1);     // B = h

    // pooling
    k_segmax<<<N_,128>>>(B, A, e0);
    k_gemm<<<128,256>>>(A, wq, T);
    k_dots<<<N_/8,256>>>(T, B, att, bq);
    k_softcx<<<N_,128>>>(B, C, e0);          // C = cx, writes g_alpha
    k_le<<<N_/8,256>>>(C, lw1, lw2, lw3);
    k_fit<<<(N_+TB-1)/TB, TB>>>(lb1, e0);
    k_topk<<<1,256>>>();
    k_xp<<<N_,128>>>(C);

    // S CSR (by source)
    k_scount<<<MB, TB>>>(e0, e1);
    k_scan8192<<<1,1024>>>(scnt, srowptr);
    k_zero_fill<<<(N_+TB-1)/TB, TB>>>();
    k_sfill<<<MB, TB>>>(e0, e1);

    // Ac = S^T A S via scatter, then fused adj = (S Ac) S^T
    k_AcScat<<<(M_*32 + TB - 1)/TB, TB>>>(e0, e1);
    cudaFuncSetAttribute(k_adjF, cudaFuncAttributeMaxDynamicSharedMemorySize, PSH_WORDS*4);
    k_adjF<<<N_/8, 256, PSH_WORDS*4>>>(adj);

    // decoder
    k_xout<<<N_,128>>>(A);                   // A = x_out
    k_gemm<<<128,256>>>(A, w3, T);
    k_aggr<<<N_,128>>>(T, b3, B, e0, 1);
    k_gemm<<<128,256>>>(B, w4, T);
    k_aggr<<<N_,128>>>(T, b4, A, e0, 1);
    k_gemm<<<128,256>>>(A, w5, T);
    k_aggr<<<N_,128>>>(T, b5, x2out, e0, 0);
}

// round 4
// speedup vs baseline: 1.4005x; 1.4005x over previous
#include <cuda_runtime.h>
#include <math.h>
#include <stdint.h>

#define N_ 8192
#define E_ 131072
#define M_ (E_ + N_)          // 139264 edges incl self loops
#define H_ 128
#define K_ 4096

// P rows in smem: two halves, each float4 per k. lo[4k+r] r=0..3, hi[4K+4k+r] r=4..7.
#define PSH_WORDS (8*K_)

// ---------------- device scratch ----------------
static __device__ float g_bufA[(size_t)N_*H_];
static __device__ float g_bufB[(size_t)N_*H_];
static __device__ float g_bufC[(size_t)N_*H_];
static __device__ float g_bufT[(size_t)N_*H_];
static __device__ float g_dis[N_];
static __device__ int   g_cnt[N_];
static __device__ int   g_ocnt[N_];
static __device__ int   g_fill[N_];
static __device__ int   g_ofill[N_];
static __device__ int   g_rowptr[N_+1];     // CSR by dst
static __device__ int   g_orowptr[N_+1];    // CSR by src
static __device__ int   g_eidx[M_];
static __device__ int   g_oeidx[M_];
static __device__ float g_alpha[M_];
static __device__ float g_aq[N_];
static __device__ float g_ah[N_];
static __device__ float g_cl1[N_], g_cl2[N_], g_cl3[N_];
static __device__ float g_fit[N_];
static __device__ int   g_sel[N_];
static __device__ int   g_col[N_];
static __device__ int   g_ncol[K_];
static __device__ float g_xp[(size_t)K_*H_];
static __device__ int   g_scnt[N_];
static __device__ int   g_srowptr[N_+1];
static __device__ int2  g_sp[M_];            // packed (col k, alpha bits), CSR by src
static __device__ float g_Ac[(size_t)K_*K_];

// ---------------- helpers ----------------
__device__ __forceinline__ int esrc_f(const int* __restrict__ e0, int e){ return (e < E_) ? e0[e] : (e - E_); }
__device__ __forceinline__ int edst_f(const int* __restrict__ e1, int e){ return (e < E_) ? e1[e] : (e - E_); }

// ---------------- small utility kernels ----------------
__global__ void k_init0(){
    int i = blockIdx.x*blockDim.x + threadIdx.x;
    if (i < N_){ g_cnt[i]=0; g_ocnt[i]=0; g_fill[i]=0; g_ofill[i]=0; g_scnt[i]=0; }
}
__global__ void k_zero_fill(){
    int i = blockIdx.x*blockDim.x + threadIdx.x;
    if (i < N_) g_fill[i]=0;
}
__global__ void k_count(const int* __restrict__ e0, const int* __restrict__ e1){
    int e = blockIdx.x*blockDim.x + threadIdx.x;
    if (e < M_){
        atomicAdd(&g_cnt[edst_f(e1,e)], 1);
        atomicAdd(&g_ocnt[esrc_f(e0,e)], 1);
    }
}
__global__ void k_dis(){
    int i = blockIdx.x*blockDim.x + threadIdx.x;
    if (i < N_) g_dis[i] = rsqrtf((float)g_cnt[i]);
}
// exclusive scan of exactly 8192 ints with 1024 threads (shfl-based)
__global__ void k_scan8192(const int* __restrict__ in, int* __restrict__ out){
    __shared__ int wsum[32];
    int tid=threadIdx.x, lane=tid&31, wid=tid>>5;
    int4 a=((const int4*)in)[tid*2], b=((const int4*)in)[tid*2+1];
    int l[8]={a.x,a.y,a.z,a.w,b.x,b.y,b.z,b.w};
    int s=0;
    #pragma unroll
    for(int q=0;q<8;q++) s+=l[q];
    int inc=s;
    #pragma unroll
    for(int o=1;o<32;o<<=1){ int t=__shfl_up_sync(0xffffffffu,inc,o); if(lane>=o) inc+=t; }
    if(lane==31) wsum[wid]=inc;
    __syncthreads();
    if (wid==0){
        int v = wsum[lane];
        #pragma unroll
        for(int o=1;o<32;o<<=1){ int t=__shfl_up_sync(0xffffffffu,v,o); if(lane>=o) v+=t; }
        wsum[lane]=v;
    }
    __syncthreads();
    int r = inc - s + (wid? wsum[wid-1]:0);
    int4 o1,o2;
    o1.x=r; r+=l[0]; o1.y=r; r+=l[1]; o1.z=r; r+=l[2]; o1.w=r; r+=l[3];
    o2.x=r; r+=l[4]; o2.y=r; r+=l[5]; o2.z=r; r+=l[6]; o2.w=r; r+=l[7];
    ((int4*)out)[tid*2]=o1; ((int4*)out)[tid*2+1]=o2;
    if (tid==1023) out[8192]=r;
}
__global__ void k_fill(const int* __restrict__ e0, const int* __restrict__ e1){
    int e = blockIdx.x*blockDim.x + threadIdx.x;
    if (e < M_){
        int d = edst_f(e1,e);
        int pos = g_rowptr[d] + atomicAdd(&g_fill[d],1);
        g_eidx[pos]=e;
        int s = esrc_f(e0,e);
        int opos = g_orowptr[s] + atomicAdd(&g_ofill[s],1);
        g_oeidx[opos]=e;
    }
}

// ---------------- 8192x128 @ 128x128 GEMM ----------------
__global__ void k_gemm(const float* __restrict__ x, const float* __restrict__ w, float* __restrict__ y){
    __shared__ __align__(16) float xs[128*64];   // [kk][r]
    int r0 = blockIdx.x*64;
    int tid = threadIdx.x;
    for (int idx=tid; idx<64*128; idx+=256){
        int r = idx >> 7;
        int kk = idx & 127;
        xs[kk*64 + r] = x[(size_t)(r0+r)*128 + kk];
    }
    __syncthreads();
    int cg = tid & 31;
    int rg = tid >> 5;
    float acc[8][4];
    #pragma unroll
    for(int r=0;r<8;r++){ acc[r][0]=0.f;acc[r][1]=0.f;acc[r][2]=0.f;acc[r][3]=0.f; }
    #pragma unroll 4
    for(int kk=0;kk<128;kk++){
        float4 wv = *(const float4*)(w + kk*128 + cg*4);
        float4 x0 = *(const float4*)(xs + kk*64 + rg*8);
        float4 x1 = *(const float4*)(xs + kk*64 + rg*8 + 4);
        float xv[8] = {x0.x,x0.y,x0.z,x0.w,x1.x,x1.y,x1.z,x1.w};
        #pragma unroll
        for(int r=0;r<8;r++){
            acc[r][0] += xv[r]*wv.x; acc[r][1] += xv[r]*wv.y;
            acc[r][2] += xv[r]*wv.z; acc[r][3] += xv[r]*wv.w;
        }
    }
    #pragma unroll
    for(int r=0;r<8;r++){
        float4 o = make_float4(acc[r][0],acc[r][1],acc[r][2],acc[r][3]);
        *(float4*)(y + (size_t)(r0+rg*8+r)*128 + cg*4) = o;
    }
}

// ---------------- GCN aggregation ----------------
__global__ void k_aggr(const float* __restrict__ y, const float* __restrict__ b,
                       float* __restrict__ out, const int* __restrict__ e0, int dotanh){
    int d = blockIdx.x, t = threadIdx.x;
    int beg = g_rowptr[d], end = g_rowptr[d+1];
    float dd = g_dis[d], acc = 0.f;
    for (int s=beg; s<end; s++){
        int e = g_eidx[s];
        int sr = esrc_f(e0,e);
        acc += y[(size_t)sr*128 + t] * (g_dis[sr]*dd);
    }
    acc += b[t];
    if (dotanh) acc = tanhf(acc);
    out[(size_t)d*128 + t] = acc;
}

__global__ void k_segmax(const float* __restrict__ h, float* __restrict__ out, const int* __restrict__ e0){
    int d = blockIdx.x, t = threadIdx.x;
    int beg = g_rowptr[d], end = g_rowptr[d+1];
    float acc = -INFINITY;
    for (int s=beg;s<end;s++){
        int sr = esrc_f(e0, g_eidx[s]);
        acc = fmaxf(acc, h[(size_t)sr*128 + t]);
    }
    out[(size_t)d*128 + t] = acc;
}

__global__ void k_dots(const float* __restrict__ xq, const float* __restrict__ h,
                       const float* __restrict__ att, const float* __restrict__ bq){
    int node = blockIdx.x*8 + (threadIdx.x>>5);
    int lane = threadIdx.x & 31;
    float s1=0.f, s2=0.f;
    for (int q=lane; q<128; q+=32){
        s1 += att[q]     * (xq[(size_t)node*128+q] + bq[q]);
        s2 += att[128+q] *  h[(size_t)node*128+q];
    }
    #pragma unroll
    for (int o=16;o;o>>=1){ s1 += __shfl_down_sync(0xffffffffu,s1,o); s2 += __shfl_down_sync(0xffffffffu,s2,o); }
    if (!lane){ g_aq[node]=s1; g_ah[node]=s2; }
}

__global__ void k_softcx(const float* __restrict__ h, float* __restrict__ cx, const int* __restrict__ e0){
    __shared__ float red[128];
    __shared__ float cache[1024];
    int d = blockIdx.x, t = threadIdx.x;
    int beg = g_rowptr[d], end = g_rowptr[d+1];
    float aqd = g_aq[d];
    float mx = -INFINITY;
    for (int s=beg+t; s<end; s+=128){
        int e = g_eidx[s];
        float sc = aqd + g_ah[esrc_f(e0,e)];
        sc = sc > 0.f ? sc : 0.2f*sc;
        if (s-beg < 1024) cache[s-beg] = sc;
        mx = fmaxf(mx, sc);
    }
    red[t]=mx; __syncthreads();
    for (int o=64;o;o>>=1){ if(t<o) red[t]=fmaxf(red[t],red[t+o]); __syncthreads(); }
    mx = red[0]; __syncthreads();
    float sm = 0.f;
    for (int s=beg+t; s<end; s+=128){
        float sc;
        if (s-beg < 1024) sc = cache[s-beg];
        else { int e=g_eidx[s]; sc = aqd + g_ah[esrc_f(e0,e)]; sc = sc>0.f? sc : 0.2f*sc; }
        float ee = __expf(sc - mx);
        if (s-beg < 1024) cache[s-beg] = ee;
        sm += ee;
    }
    red[t]=sm; __syncthreads();
    for (int o=64;o;o>>=1){ if(t<o) red[t]+=red[t+o]; __syncthreads(); }
    float inv = 1.f/red[0];
    for (int s=beg+t; s<end; s+=128){
        int e = g_eidx[s];
        float ee;
        if (s-beg < 1024) ee = cache[s-beg];
        else { float sc = aqd + g_ah[esrc_f(e0,e)]; sc = sc>0.f? sc:0.2f*sc; ee = __expf(sc-mx); }
        float a = ee*inv;
        g_alpha[e] = a;
        if (s-beg < 1024) cache[s-beg] = a;
    }
    __syncthreads();
    float acc = 0.f;
    for (int s=beg; s<end; s++){
        int e = g_eidx[s];
        float a = (s-beg < 1024) ? cache[s-beg] : g_alpha[e];
        acc += a * h[(size_t)esrc_f(e0,e)*128 + t];
    }
    cx[(size_t)d*128 + t] = acc;
}

__global__ void k_le(const float* __restrict__ cx, const float* __restrict__ lw1,
                     const float* __restrict__ lw2, const float* __restrict__ lw3){
    int node = blockIdx.x*8 + (threadIdx.x>>5);
    int lane = threadIdx.x & 31;
    float s1=0.f,s2=0.f,s3=0.f;
    for (int q=lane;q<128;q+=32){
        float v = cx[(size_t)node*128+q];
        s1 += v*lw1[q]; s2 += v*lw2[q]; s3 += v*lw3[q];
    }
    #pragma unroll
    for (int o=16;o;o>>=1){
        s1 += __shfl_down_sync(0xffffffffu,s1,o);
        s2 += __shfl_down_sync(0xffffffffu,s2,o);
        s3 += __shfl_down_sync(0xffffffffu,s3,o);
    }
    if (!lane){ g_cl1[node]=s1; g_cl2[node]=s2; g_cl3[node]=s3; }
}
__global__ void k_fit(const float* __restrict__ lb1, const int* __restrict__ e0){
    int d = blockIdx.x*blockDim.x + threadIdx.x;
    if (d >= N_) return;
    int beg=g_rowptr[d], end=g_rowptr[d+1];
    float s = 0.f;
    for (int q=beg;q<end;q++) s += g_cl3[esrc_f(e0, g_eidx[q])];
    float aggr = (float)(end-beg)*g_cl2[d] - s;
    float z = g_cl1[d] + lb1[0] + aggr;
    g_fit[d] = 1.f/(1.f + __expf(-z));
}

// ---------------- top-K via 4x8-bit histogram radix select (256 threads) ----------------
__global__ void k_topk(){
    __shared__ int hist[256];
    __shared__ int wred[8];
    __shared__ unsigned s_pref;
    __shared__ int s_need;
    int tid=threadIdx.x, lane=tid&31, wid=tid>>5;
    if (tid==0){ s_pref=0u; s_need=K_; }
    unsigned keys[32];
    #pragma unroll
    for (int q=0;q<32;q++){
        unsigned u=__float_as_uint(g_fit[tid*32+q]);
        keys[q] = (u & 0x80000000u) ? ~u : (u | 0x80000000u);
    }
    __syncthreads();
    for (int round=0; round<4; round++){
        int shift = 24 - 8*round;
        hist[tid]=0;
        __syncthreads();
        unsigned pref = s_pref;
        #pragma unroll
        for (int q=0;q<32;q++){
            unsigned k = keys[q];
            bool match = (round==0) || ((k >> (shift+8)) == (pref >> (shift+8)));
            if (match) atomicAdd(&hist[(k>>shift)&0xFFu], 1);
        }
        __syncthreads();
        int mine = hist[255-tid];
        int v = mine;
        #pragma unroll
        for (int o=1;o<32;o<<=1){ int t2=__shfl_up_sync(0xffffffffu,v,o); if(lane>=o) v+=t2; }
        if (lane==31) wred[wid]=v;
        __syncthreads();
        int woff=0;
        #pragma unroll
        for (int w=0;w<8;w++) if (w<wid) woff+=wred[w];
        v += woff;
        int need0 = s_need;
        int vex = v - mine;
        if (v >= need0 && vex < need0){
            s_pref = s_pref | ((unsigned)(255-tid) << shift);
            s_need = need0 - vex;
        }
        __syncthreads();
    }
    unsigned thr = s_pref;
    int need = s_need;
    int tcnt=0;
    #pragma unroll
    for (int q=0;q<32;q++) tcnt += (keys[q]==thr);
    int v=tcnt;
    #pragma unroll
    for (int o=1;o<32;o<<=1){ int t2=__shfl_up_sync(0xffffffffu,v,o); if(lane>=o) v+=t2; }
    if (lane==31) wred[wid]=v;
    __syncthreads();
    int woff=0;
    #pragma unroll
    for (int w=0;w<8;w++) if (w<wid) woff+=wred[w];
    int rank = v - tcnt + woff;
    int scnt=0;
    int selq[32];
    #pragma unroll
    for (int q=0;q<32;q++){
        unsigned k=keys[q];
        bool eq = (k==thr);
        int s = (k>thr) || (eq && rank < need);
        if (eq) rank++;
        selq[q]=s;
        g_sel[tid*32+q]=s;
        scnt+=s;
    }
    __syncthreads();
    v=scnt;
    #pragma unroll
    for (int o=1;o<32;o<<=1){ int t2=__shfl_up_sync(0xffffffffu,v,o); if(lane>=o) v+=t2; }
    if (lane==31) wred[wid]=v;
    __syncthreads();
    woff=0;
    #pragma unroll
    for (int w=0;w<8;w++) if (w<wid) woff+=wred[w];
    int base = v - scnt + woff;
    #pragma unroll
    for (int q=0;q<32;q++){
        int i = tid*32+q;
        if (selq[q]){ g_col[i]=base; g_ncol[base]=i; base++; }
        else g_col[i]=-1;
    }
}

__global__ void k_xp(const float* __restrict__ cx){
    int i = blockIdx.x, t = threadIdx.x;
    if (!g_sel[i]) return;
    g_xp[(size_t)g_col[i]*128 + t] = cx[(size_t)i*128 + t] * g_fit[i];
}

// ---------------- S CSR (by source) with packed entries ----------------
__global__ void k_scount(const int* __restrict__ e0, const int* __restrict__ e1){
    int e = blockIdx.x*blockDim.x + threadIdx.x;
    if (e < M_){
        int d = edst_f(e1,e);
        if (g_sel[d]) atomicAdd(&g_scnt[esrc_f(e0,e)], 1);
    }
}
__global__ void k_sfill(const int* __restrict__ e0, const int* __restrict__ e1){
    int e = blockIdx.x*blockDim.x + threadIdx.x;
    if (e < M_){
        int d = edst_f(e1,e);
        if (g_sel[d]){
            int s = esrc_f(e0,e);
            int pos = g_srowptr[s] + atomicAdd(&g_fill[s],1);
            g_sp[pos] = make_int2(g_col[d], __float_as_int(g_alpha[e]));
        }
    }
}

// ---------------- Ac row gather with smem accumulator ----------------
// Ac[k,m] = sum_{e=(s->d_k)} alpha_e * sum_{f=(s->j)} sum_{(m,a) in S_j} a
__global__ void k_AcRow(const int* __restrict__ e0, const int* __restrict__ e1){
    __shared__ float acc[K_];
    int k = blockIdx.x, tid = threadIdx.x;
    int lane = tid & 31, w = tid >> 5, nw = blockDim.x >> 5;
    for (int m=tid; m<K_; m+=blockDim.x) acc[m]=0.f;
    __syncthreads();
    int d = g_ncol[k];
    int ib = g_rowptr[d], ie = g_rowptr[d+1];
    for (int p=ib+w; p<ie; p+=nw){
        int e = g_eidx[p];
        int s = esrc_f(e0,e);
        float ae = g_alpha[e];
        int ob = g_orowptr[s], oe = g_orowptr[s+1];
        for (int f=ob; f<oe; f++){
            int e2 = g_oeidx[f];
            int j = edst_f(e1,e2);
            int sb = g_srowptr[j], se = g_srowptr[j+1];
            for (int q=sb+lane; q<se; q+=32){
                int2 kp = g_sp[q];
                atomicAdd(&acc[kp.x], ae*__int_as_float(kp.y));
            }
        }
    }
    __syncthreads();
    float* orow = &g_Ac[(size_t)k*K_];
    for (int m=tid; m<K_; m+=blockDim.x) orow[m]=acc[m];
}

// ---------------- fused: build 8 P-rows (registers->smem), then adj = P S^T ----------------
__global__ void k_adjF(float* __restrict__ adj){
    extern __shared__ __align__(16) float Psh[];   // lo[4k + r<4], hi[4K + 4k + (r-4)]
    int i0 = blockIdx.x*8, tid = threadIdx.x;      // 512 threads
    #pragma unroll 1
    for (int r=0;r<8;r++){
        float acc[8];
        #pragma unroll
        for (int c=0;c<8;c++) acc[c]=0.f;
        int qb=g_srowptr[i0+r], qe=g_srowptr[i0+r+1];
        for (int q=qb;q<qe;q++){
            int2 kp = g_sp[q];
            float a = __int_as_float(kp.y);
            const float* row = &g_Ac[(size_t)kp.x*K_] + tid;
            #pragma unroll
            for (int c=0;c<8;c++) acc[c] += a*row[c*512];
        }
        float* half = Psh + ((r>=4) ? 4*K_ : 0);
        int rr = r & 3;
        #pragma unroll
        for (int c=0;c<8;c++){
            int k = tid + c*512;
            half[4*k + rr] = acc[c];
        }
    }
    __syncthreads();
    for (int j=tid; j<N_; j+=512){
        float b0=0,b1=0,b2=0,b3=0,b4=0,b5=0,b6=0,b7=0;
        int qb = g_srowptr[j], qe = g_srowptr[j+1];
        for (int q=qb;q<qe;q++){
            int2 kp = g_sp[q];
            float a = __int_as_float(kp.y);
            float4 p0 = *(const float4*)&Psh[4*kp.x];
            float4 p1 = *(const float4*)&Psh[4*K_ + 4*kp.x];
            b0 += a*p0.x; b1 += a*p0.y; b2 += a*p0.z; b3 += a*p0.w;
            b4 += a*p1.x; b5 += a*p1.y; b6 += a*p1.z; b7 += a*p1.w;
        }
        adj[(size_t)(i0+0)*N_ + j]=b0; adj[(size_t)(i0+1)*N_ + j]=b1;
        adj[(size_t)(i0+2)*N_ + j]=b2; adj[(size_t)(i0+3)*N_ + j]=b3;
        adj[(size_t)(i0+4)*N_ + j]=b4; adj[(size_t)(i0+5)*N_ + j]=b5;
        adj[(size_t)(i0+6)*N_ + j]=b6; adj[(size_t)(i0+7)*N_ + j]=b7;
    }
}

// x_out[i,:] = sum over S row i: alpha*xp[k,:]
__global__ void k_xout(float* __restrict__ out){
    int i = blockIdx.x, t = threadIdx.x;
    float acc = 0.f;
    for (int q=g_srowptr[i]; q<g_srowptr[i+1]; q++){
        int2 kp = g_sp[q];
        acc += __int_as_float(kp.y) * g_xp[(size_t)kp.x*128 + t];
    }
    out[(size_t)i*128 + t] = acc;
}

// ---------------- host ----------------
extern "C" void kernel_launch(void* const* d_in, const int* in_sizes, int n_in,
                              void* d_out, int out_size){
    const float* nodes = (const float*)d_in[0];
    const int*   edges = (const int*)d_in[1];
    const int* e0 = edges;
    const int* e1 = edges + E_;
    const float* w1 = (const float*)d_in[3];  const float* b1 = (const float*)d_in[4];
    const float* w2 = (const float*)d_in[5];  const float* b2 = (const float*)d_in[6];
    const float* w3 = (const float*)d_in[7];  const float* b3 = (const float*)d_in[8];
    const float* w4 = (const float*)d_in[9];  const float* b4 = (const float*)d_in[10];
    const float* w5 = (const float*)d_in[11]; const float* b5 = (const float*)d_in[12];
    const float* wq = (const float*)d_in[13]; const float* bq = (const float*)d_in[14];
    const float* att = (const float*)d_in[15];
    const float* lw1 = (const float*)d_in[16]; const float* lb1 = (const float*)d_in[17];
    const float* lw2 = (const float*)d_in[18]; const float* lw3 = (const float*)d_in[19];

    float* out = (float*)d_out;
    float* x2out = out;
    float* adj  = out + (size_t)N_*H_;

    float *A,*B,*C,*T; int *cnt,*ocnt,*rowptr,*orowptr,*scnt,*srowptr;
    cudaGetSymbolAddress((void**)&A, g_bufA);
    cudaGetSymbolAddress((void**)&B, g_bufB);
    cudaGetSymbolAddress((void**)&C, g_bufC);
    cudaGetSymbolAddress((void**)&T, g_bufT);
    cudaGetSymbolAddress((void**)&cnt, g_cnt);
    cudaGetSymbolAddress((void**)&ocnt, g_ocnt);
    cudaGetSymbolAddress((void**)&rowptr, g_rowptr);
    cudaGetSymbolAddress((void**)&orowptr, g_orowptr);
    cudaGetSymbolAddress((void**)&scnt, g_scnt);
    cudaGetSymbolAddress((void**)&srowptr, g_srowptr);

    const int TB = 256;
    const int MB = (M_ + TB - 1)/TB;

    // graph prep: dst-CSR + src-CSR
    k_init0<<<(N_+TB-1)/TB, TB>>>();
    k_count<<<MB, TB>>>(e0, e1);
    k_dis<<<(N_+TB-1)/TB, TB>>>();
    k_scan8192<<<1,1024>>>(cnt, rowptr);
    k_scan8192<<<1,1024>>>(ocnt, orowptr);
    k_fill<<<MB, TB>>>(e0, e1);

    // encoder
    k_gemm<<<128,256>>>(nodes, w1, T);
    k_aggr<<<N_,128>>>(T, b1, A, e0, 1);
    k_gemm<<<128,256>>>(A, w2, T);
    k_aggr<<<N_,128>>>(T, b2, B, e0, 1);     // B = h

    // pooling
    k_segmax<<<N_,128>>>(B, A, e0);
    k_gemm<<<128,256>>>(A, wq, T);
    k_dots<<<N_/8,256>>>(T, B, att, bq);
    k_softcx<<<N_,128>>>(B, C, e0);          // C = cx, writes g_alpha
    k_le<<<N_/8,256>>>(C, lw1, lw2, lw3);
    k_fit<<<(N_+TB-1)/TB, TB>>>(lb1, e0);
    k_topk<<<1,256>>>();
    k_xp<<<N_,128>>>(C);

    // S CSR (by source)
    k_scount<<<MB, TB>>>(e0, e1);
    k_scan8192<<<1,1024>>>(scnt, srowptr);
    k_zero_fill<<<(N_+TB-1)/TB, TB>>>();
    k_sfill<<<MB, TB>>>(e0, e1);

    // Ac rows via smem accumulation, then fused adj = (S Ac) S^T
    k_AcRow<<<K_, 256>>>(e0, e1);
    cudaFuncSetAttribute(k_adjF, cudaFuncAttributeMaxDynamicSharedMemorySize, PSH_WORDS*4);
    k_adjF<<<N_/8, 512, PSH_WORDS*4>>>(adj);

    // decoder
    k_xout<<<N_,128>>>(A);                   // A = x_out
    k_gemm<<<128,256>>>(A, w3, T);
    k_aggr<<<N_,128>>>(T, b3, B, e0, 1);
    k_gemm<<<128,256>>>(B, w4, T);
    k_aggr<<<N_,128>>>(T, b4, A, e0, 1);
    k_gemm<<<128,256>>>(A, w5, T);
    k_aggr<<<N_,128>>>(T, b5, x2out, e0, 0);
}

// round 5
// speedup vs baseline: 1.5035x; 1.0736x over previous
#include <cuda_runtime.h>
#include <math.h>
#include <stdint.h>

#define N_ 8192
#define E_ 131072
#define M_ (E_ + N_)          // 139264 edges incl self loops
#define H_ 128
#define K_ 4096

#define PSH_WORDS (8*K_)

// ---------------- device scratch ----------------
static __device__ float g_bufA[(size_t)N_*H_];
static __device__ float g_bufB[(size_t)N_*H_];
static __device__ float g_bufC[(size_t)N_*H_];
static __device__ float g_bufT[(size_t)N_*H_];
static __device__ float g_dis[N_];
static __device__ int   g_cnt[N_];
static __device__ int   g_ocnt[N_];
static __device__ int   g_fill[N_];
static __device__ int   g_ofill[N_];
static __device__ int   g_rowptr[N_+1];     // CSR by dst
static __device__ int   g_orowptr[N_+1];    // CSR by src
static __device__ int2  g_adj[M_];          // per dst-CSR pos: (src, norm bits)
static __device__ int   g_oadj[M_];         // per src-CSR pos: dst
static __device__ float g_alpha[M_];        // per dst-CSR pos
static __device__ float g_aq[N_];
static __device__ float g_ah[N_];
static __device__ float g_cl1[N_], g_cl2[N_], g_cl3[N_];
static __device__ float g_fit[N_];
static __device__ int   g_sel[N_];
static __device__ int   g_col[N_];
static __device__ int   g_ncol[K_];
static __device__ float g_xp[(size_t)K_*H_];
static __device__ int   g_scnt[N_];
static __device__ int   g_srowptr[N_+1];
static __device__ int2  g_sp[M_];            // packed (col k, alpha bits), CSR by src
static __device__ float g_Ac[(size_t)K_*K_];

// ---------------- helpers ----------------
__device__ __forceinline__ int esrc_f(const int* __restrict__ e0, int e){ return (e < E_) ? e0[e] : (e - E_); }
__device__ __forceinline__ int edst_f(const int* __restrict__ e1, int e){ return (e < E_) ? e1[e] : (e - E_); }

// ---------------- small utility kernels ----------------
__global__ void k_init0(){
    int i = blockIdx.x*blockDim.x + threadIdx.x;
    if (i < N_){ g_cnt[i]=0; g_ocnt[i]=0; g_fill[i]=0; g_ofill[i]=0; g_scnt[i]=0; }
}
__global__ void k_zero_fill(){
    int i = blockIdx.x*blockDim.x + threadIdx.x;
    if (i < N_) g_fill[i]=0;
}
__global__ void k_count(const int* __restrict__ e0, const int* __restrict__ e1){
    int e = blockIdx.x*blockDim.x + threadIdx.x;
    if (e < M_){
        atomicAdd(&g_cnt[edst_f(e1,e)], 1);
        atomicAdd(&g_ocnt[esrc_f(e0,e)], 1);
    }
}
__global__ void k_dis(){
    int i = blockIdx.x*blockDim.x + threadIdx.x;
    if (i < N_) g_dis[i] = rsqrtf((float)g_cnt[i]);
}
// exclusive scan of exactly 8192 ints with 1024 threads (shfl-based)
__global__ void k_scan8192(const int* __restrict__ in, int* __restrict__ out){
    __shared__ int wsum[32];
    int tid=threadIdx.x, lane=tid&31, wid=tid>>5;
    int4 a=((const int4*)in)[tid*2], b=((const int4*)in)[tid*2+1];
    int l[8]={a.x,a.y,a.z,a.w,b.x,b.y,b.z,b.w};
    int s=0;
    #pragma unroll
    for(int q=0;q<8;q++) s+=l[q];
    int inc=s;
    #pragma unroll
    for(int o=1;o<32;o<<=1){ int t=__shfl_up_sync(0xffffffffu,inc,o); if(lane>=o) inc+=t; }
    if(lane==31) wsum[wid]=inc;
    __syncthreads();
    if (wid==0){
        int v = wsum[lane];
        #pragma unroll
        for(int o=1;o<32;o<<=1){ int t=__shfl_up_sync(0xffffffffu,v,o); if(lane>=o) v+=t; }
        wsum[lane]=v;
    }
    __syncthreads();
    int r = inc - s + (wid? wsum[wid-1]:0);
    int4 o1,o2;
    o1.x=r; r+=l[0]; o1.y=r; r+=l[1]; o1.z=r; r+=l[2]; o1.w=r; r+=l[3];
    o2.x=r; r+=l[4]; o2.y=r; r+=l[5]; o2.z=r; r+=l[6]; o2.w=r; r+=l[7];
    ((int4*)out)[tid*2]=o1; ((int4*)out)[tid*2+1]=o2;
    if (tid==1023) out[8192]=r;
}
// build positional adjacency with folded norm
__global__ void k_fill(const int* __restrict__ e0, const int* __restrict__ e1){
    int e = blockIdx.x*blockDim.x + threadIdx.x;
    if (e < M_){
        int s = esrc_f(e0,e);
        int d = edst_f(e1,e);
        float nm = g_dis[s]*g_dis[d];
        int pos = g_rowptr[d] + atomicAdd(&g_fill[d],1);
        g_adj[pos] = make_int2(s, __float_as_int(nm));
        int opos = g_orowptr[s] + atomicAdd(&g_ofill[s],1);
        g_oadj[opos] = d;
    }
}

// ---------------- 8192x128 @ 128x128 GEMM ----------------
__global__ void k_gemm(const float* __restrict__ x, const float* __restrict__ w, float* __restrict__ y){
    __shared__ __align__(16) float xs[128*64];   // [kk][r]
    int r0 = blockIdx.x*64;
    int tid = threadIdx.x;
    for (int idx=tid; idx<64*128; idx+=256){
        int r = idx >> 7;
        int kk = idx & 127;
        xs[kk*64 + r] = x[(size_t)(r0+r)*128 + kk];
    }
    __syncthreads();
    int cg = tid & 31;
    int rg = tid >> 5;
    float acc[8][4];
    #pragma unroll
    for(int r=0;r<8;r++){ acc[r][0]=0.f;acc[r][1]=0.f;acc[r][2]=0.f;acc[r][3]=0.f; }
    #pragma unroll 4
    for(int kk=0;kk<128;kk++){
        float4 wv = *(const float4*)(w + kk*128 + cg*4);
        float4 x0 = *(const float4*)(xs + kk*64 + rg*8);
        float4 x1 = *(const float4*)(xs + kk*64 + rg*8 + 4);
        float xv[8] = {x0.x,x0.y,x0.z,x0.w,x1.x,x1.y,x1.z,x1.w};
        #pragma unroll
        for(int r=0;r<8;r++){
            acc[r][0] += xv[r]*wv.x; acc[r][1] += xv[r]*wv.y;
            acc[r][2] += xv[r]*wv.z; acc[r][3] += xv[r]*wv.w;
        }
    }
    #pragma unroll
    for(int r=0;r<8;r++){
        float4 o = make_float4(acc[r][0],acc[r][1],acc[r][2],acc[r][3]);
        *(float4*)(y + (size_t)(r0+rg*8+r)*128 + cg*4) = o;
    }
}

// ---------------- GCN aggregation: warp per dst, float4 lanes ----------------
__global__ void k_aggr(const float* __restrict__ y, const float* __restrict__ b,
                       float* __restrict__ out, int dotanh){
    int d = blockIdx.x*8 + (threadIdx.x>>5);
    int lane = threadIdx.x & 31;
    const float4* y4 = (const float4*)y;
    float4 acc = ((const float4*)b)[lane];
    int beg = g_rowptr[d], end = g_rowptr[d+1];
    int p = beg;
    for (; p+1 < end; p += 2){
        int2 a0 = g_adj[p], a1 = g_adj[p+1];
        float n0 = __int_as_float(a0.y), n1 = __int_as_float(a1.y);
        float4 v0 = y4[(size_t)a0.x*32 + lane];
        float4 v1 = y4[(size_t)a1.x*32 + lane];
        acc.x += n0*v0.x + n1*v1.x;
        acc.y += n0*v0.y + n1*v1.y;
        acc.z += n0*v0.z + n1*v1.z;
        acc.w += n0*v0.w + n1*v1.w;
    }
    if (p < end){
        int2 a0 = g_adj[p];
        float n0 = __int_as_float(a0.y);
        float4 v0 = y4[(size_t)a0.x*32 + lane];
        acc.x += n0*v0.x; acc.y += n0*v0.y; acc.z += n0*v0.z; acc.w += n0*v0.w;
    }
    if (dotanh){
        acc.x = tanhf(acc.x); acc.y = tanhf(acc.y);
        acc.z = tanhf(acc.z); acc.w = tanhf(acc.w);
    }
    ((float4*)out)[(size_t)d*32 + lane] = acc;
}

__global__ void k_segmax(const float* __restrict__ h, float* __restrict__ out){
    int d = blockIdx.x*8 + (threadIdx.x>>5);
    int lane = threadIdx.x & 31;
    const float4* h4 = (const float4*)h;
    float4 acc = make_float4(-INFINITY,-INFINITY,-INFINITY,-INFINITY);
    int beg = g_rowptr[d], end = g_rowptr[d+1];
    for (int p=beg; p<end; p++){
        float4 v = h4[(size_t)g_adj[p].x*32 + lane];
        acc.x = fmaxf(acc.x,v.x); acc.y = fmaxf(acc.y,v.y);
        acc.z = fmaxf(acc.z,v.z); acc.w = fmaxf(acc.w,v.w);
    }
    ((float4*)out)[(size_t)d*32 + lane] = acc;
}

__global__ void k_dots(const float* __restrict__ xq, const float* __restrict__ h,
                       const float* __restrict__ att, const float* __restrict__ bq){
    int node = blockIdx.x*8 + (threadIdx.x>>5);
    int lane = threadIdx.x & 31;
    const float4* xq4 = (const float4*)xq;
    const float4* h4  = (const float4*)h;
    const float4* at4 = (const float4*)att;
    const float4* bq4 = (const float4*)bq;
    float4 a1 = at4[lane], a2 = at4[32+lane];
    float4 xv = xq4[(size_t)node*32+lane], bv = bq4[lane], hv = h4[(size_t)node*32+lane];
    float s1 = a1.x*(xv.x+bv.x) + a1.y*(xv.y+bv.y) + a1.z*(xv.z+bv.z) + a1.w*(xv.w+bv.w);
    float s2 = a2.x*hv.x + a2.y*hv.y + a2.z*hv.z + a2.w*hv.w;
    #pragma unroll
    for (int o=16;o;o>>=1){ s1 += __shfl_down_sync(0xffffffffu,s1,o); s2 += __shfl_down_sync(0xffffffffu,s2,o); }
    if (!lane){ g_aq[node]=s1; g_ah[node]=s2; }
}

// per-dst softmax over in-edges (positional alpha) + cluster rep cx
__global__ void k_softcx(const float* __restrict__ h, float* __restrict__ cx){
    __shared__ float red[128];
    __shared__ float cache[1024];
    __shared__ int   scache[1024];
    int d = blockIdx.x, t = threadIdx.x;
    int beg = g_rowptr[d], end = g_rowptr[d+1];
    float aqd = g_aq[d];
    float mx = -INFINITY;
    for (int s=beg+t; s<end; s+=128){
        int src = g_adj[s].x;
        float sc = aqd + g_ah[src];
        sc = sc > 0.f ? sc : 0.2f*sc;
        if (s-beg < 1024){ cache[s-beg] = sc; scache[s-beg] = src; }
        mx = fmaxf(mx, sc);
    }
    red[t]=mx; __syncthreads();
    for (int o=64;o;o>>=1){ if(t<o) red[t]=fmaxf(red[t],red[t+o]); __syncthreads(); }
    mx = red[0]; __syncthreads();
    float sm = 0.f;
    for (int s=beg+t; s<end; s+=128){
        float sc;
        if (s-beg < 1024) sc = cache[s-beg];
        else { float v = aqd + g_ah[g_adj[s].x]; sc = v>0.f? v : 0.2f*v; }
        float ee = __expf(sc - mx);
        if (s-beg < 1024) cache[s-beg] = ee;
        sm += ee;
    }
    red[t]=sm; __syncthreads();
    for (int o=64;o;o>>=1){ if(t<o) red[t]+=red[t+o]; __syncthreads(); }
    float inv = 1.f/red[0];
    for (int s=beg+t; s<end; s+=128){
        float ee;
        if (s-beg < 1024) ee = cache[s-beg];
        else { float v = aqd + g_ah[g_adj[s].x]; v = v>0.f? v:0.2f*v; ee = __expf(v-mx); }
        float a = ee*inv;
        g_alpha[s] = a;
        if (s-beg < 1024) cache[s-beg] = a;
    }
    __syncthreads();
    float acc = 0.f;
    for (int s=beg; s<end; s++){
        float a; int src;
        if (s-beg < 1024){ a = cache[s-beg]; src = scache[s-beg]; }
        else { a = g_alpha[s]; src = g_adj[s].x; }
        acc += a * h[(size_t)src*128 + t];
    }
    cx[(size_t)d*128 + t] = acc;
}

__global__ void k_le(const float* __restrict__ cx, const float* __restrict__ lw1,
                     const float* __restrict__ lw2, const float* __restrict__ lw3){
    int node = blockIdx.x*8 + (threadIdx.x>>5);
    int lane = threadIdx.x & 31;
    const float4* c4 = (const float4*)cx;
    const float4* w14 = (const float4*)lw1;
    const float4* w24 = (const float4*)lw2;
    const float4* w34 = (const float4*)lw3;
    float4 v = c4[(size_t)node*32+lane];
    float4 w1v = w14[lane], w2v = w24[lane], w3v = w34[lane];
    float s1 = v.x*w1v.x + v.y*w1v.y + v.z*w1v.z + v.w*w1v.w;
    float s2 = v.x*w2v.x + v.y*w2v.y + v.z*w2v.z + v.w*w2v.w;
    float s3 = v.x*w3v.x + v.y*w3v.y + v.z*w3v.z + v.w*w3v.w;
    #pragma unroll
    for (int o=16;o;o>>=1){
        s1 += __shfl_down_sync(0xffffffffu,s1,o);
        s2 += __shfl_down_sync(0xffffffffu,s2,o);
        s3 += __shfl_down_sync(0xffffffffu,s3,o);
    }
    if (!lane){ g_cl1[node]=s1; g_cl2[node]=s2; g_cl3[node]=s3; }
}
__global__ void k_fit(const float* __restrict__ lb1){
    int d = blockIdx.x*blockDim.x + threadIdx.x;
    if (d >= N_) return;
    int beg=g_rowptr[d], end=g_rowptr[d+1];
    float s = 0.f;
    for (int q=beg;q<end;q++) s += g_cl3[g_adj[q].x];
    float aggr = (float)(end-beg)*g_cl2[d] - s;
    float z = g_cl1[d] + lb1[0] + aggr;
    g_fit[d] = 1.f/(1.f + __expf(-z));
}

// ---------------- top-K via 4x8-bit histogram radix select ----------------
__global__ void k_topk(){
    __shared__ int hist[256];
    __shared__ int wred[8];
    __shared__ unsigned s_pref;
    __shared__ int s_need;
    int tid=threadIdx.x, lane=tid&31, wid=tid>>5;
    if (tid==0){ s_pref=0u; s_need=K_; }
    unsigned keys[32];
    #pragma unroll
    for (int q=0;q<32;q++){
        unsigned u=__float_as_uint(g_fit[tid*32+q]);
        keys[q] = (u & 0x80000000u) ? ~u : (u | 0x80000000u);
    }
    __syncthreads();
    for (int round=0; round<4; round++){
        int shift = 24 - 8*round;
        hist[tid]=0;
        __syncthreads();
        unsigned pref = s_pref;
        #pragma unroll
        for (int q=0;q<32;q++){
            unsigned k = keys[q];
            bool match = (round==0) || ((k >> (shift+8)) == (pref >> (shift+8)));
            if (match) atomicAdd(&hist[(k>>shift)&0xFFu], 1);
        }
        __syncthreads();
        int mine = hist[255-tid];
        int v = mine;
        #pragma unroll
        for (int o=1;o<32;o<<=1){ int t2=__shfl_up_sync(0xffffffffu,v,o); if(lane>=o) v+=t2; }
        if (lane==31) wred[wid]=v;
        __syncthreads();
        int woff=0;
        #pragma unroll
        for (int w=0;w<8;w++) if (w<wid) woff+=wred[w];
        v += woff;
        int need0 = s_need;
        int vex = v - mine;
        if (v >= need0 && vex < need0){
            s_pref = s_pref | ((unsigned)(255-tid) << shift);
            s_need = need0 - vex;
        }
        __syncthreads();
    }
    unsigned thr = s_pref;
    int need = s_need;
    int tcnt=0;
    #pragma unroll
    for (int q=0;q<32;q++) tcnt += (keys[q]==thr);
    int v=tcnt;
    #pragma unroll
    for (int o=1;o<32;o<<=1){ int t2=__shfl_up_sync(0xffffffffu,v,o); if(lane>=o) v+=t2; }
    if (lane==31) wred[wid]=v;
    __syncthreads();
    int woff=0;
    #pragma unroll
    for (int w=0;w<8;w++) if (w<wid) woff+=wred[w];
    int rank = v - tcnt + woff;
    int scnt=0;
    int selq[32];
    #pragma unroll
    for (int q=0;q<32;q++){
        unsigned k=keys[q];
        bool eq = (k==thr);
        int s = (k>thr) || (eq && rank < need);
        if (eq) rank++;
        selq[q]=s;
        g_sel[tid*32+q]=s;
        scnt+=s;
    }
    __syncthreads();
    v=scnt;
    #pragma unroll
    for (int o=1;o<32;o<<=1){ int t2=__shfl_up_sync(0xffffffffu,v,o); if(lane>=o) v+=t2; }
    if (lane==31) wred[wid]=v;
    __syncthreads();
    woff=0;
    #pragma unroll
    for (int w=0;w<8;w++) if (w<wid) woff+=wred[w];
    int base = v - scnt + woff;
    #pragma unroll
    for (int q=0;q<32;q++){
        int i = tid*32+q;
        if (selq[q]){ g_col[i]=base; g_ncol[base]=i; base++; }
        else g_col[i]=-1;
    }
}

__global__ void k_xp(const float* __restrict__ cx){
    int i = blockIdx.x, t = threadIdx.x;
    if (!g_sel[i]) return;
    g_xp[(size_t)g_col[i]*128 + t] = cx[(size_t)i*128 + t] * g_fit[i];
}

// ---------------- S CSR (by source): count + fill from dst rows ----------------
__global__ void k_scount(){
    int d = blockIdx.x*blockDim.x + threadIdx.x;
    if (d >= N_ || !g_sel[d]) return;
    int beg=g_rowptr[d], end=g_rowptr[d+1];
    for (int p=beg;p<end;p++) atomicAdd(&g_scnt[g_adj[p].x], 1);
}
__global__ void k_sfill(){
    int d = blockIdx.x*blockDim.x + threadIdx.x;
    if (d >= N_ || !g_sel[d]) return;
    int colk = g_col[d];
    int beg=g_rowptr[d], end=g_rowptr[d+1];
    for (int p=beg;p<end;p++){
        int s = g_adj[p].x;
        int pos = g_srowptr[s] + atomicAdd(&g_fill[s],1);
        g_sp[pos] = make_int2(colk, __float_as_int(g_alpha[p]));
    }
}

// ---------------- Ac row gather with smem accumulator ----------------
__global__ void k_AcRow(){
    __shared__ float acc[K_];
    int k = blockIdx.x, tid = threadIdx.x;
    int lane = tid & 31, w = tid >> 5, nw = blockDim.x >> 5;
    for (int m=tid; m<K_; m+=blockDim.x) acc[m]=0.f;
    __syncthreads();
    int d = g_ncol[k];
    int ib = g_rowptr[d], ie = g_rowptr[d+1];
    for (int p=ib+w; p<ie; p+=nw){
        int s = g_adj[p].x;
        float ae = g_alpha[p];
        int ob = g_orowptr[s], oe = g_orowptr[s+1];
        for (int f=ob; f<oe; f++){
            int j = g_oadj[f];
            int sb = g_srowptr[j], se = g_srowptr[j+1];
            for (int q=sb+lane; q<se; q+=32){
                int2 kp = g_sp[q];
                atomicAdd(&acc[kp.x], ae*__int_as_float(kp.y));
            }
        }
    }
    __syncthreads();
    float* orow = &g_Ac[(size_t)k*K_];
    for (int m=tid; m<K_; m+=blockDim.x) orow[m]=acc[m];
}

// ---------------- fused: build 8 P-rows (registers->smem), then adj = P S^T ----------------
__global__ void k_adjF(float* __restrict__ adj){
    extern __shared__ __align__(16) float Psh[];   // lo[4k + r<4], hi[4K + 4k + (r-4)]
    int i0 = blockIdx.x*8, tid = threadIdx.x;      // 512 threads
    const float4* Ac4 = (const float4*)g_Ac;
    #pragma unroll 1
    for (int r=0;r<8;r++){
        float4 a0 = make_float4(0,0,0,0), a1 = make_float4(0,0,0,0);
        int qb=g_srowptr[i0+r], qe=g_srowptr[i0+r+1];
        for (int q=qb;q<qe;q++){
            int2 kp = g_sp[q];
            float a = __int_as_float(kp.y);
            const float4* row = Ac4 + (size_t)kp.x*(K_/4);
            float4 v0 = row[tid], v1 = row[tid+512];
            a0.x += a*v0.x; a0.y += a*v0.y; a0.z += a*v0.z; a0.w += a*v0.w;
            a1.x += a*v1.x; a1.y += a*v1.y; a1.z += a*v1.z; a1.w += a*v1.w;
        }
        float* half = Psh + ((r>=4) ? 4*K_ : 0);
        int rr = r & 3;
        // group g covers cols 4g..4g+3 -> positions half[4*(4g+u)+rr]
        int g0 = tid, g1 = tid+512;
        half[16*g0 + 0 + rr] = a0.x; half[16*g0 + 4 + rr] = a0.y;
        half[16*g0 + 8 + rr] = a0.z; half[16*g0 +12 + rr] = a0.w;
        half[16*g1 + 0 + rr] = a1.x; half[16*g1 + 4 + rr] = a1.y;
        half[16*g1 + 8 + rr] = a1.z; half[16*g1 +12 + rr] = a1.w;
    }
    __syncthreads();
    for (int j=tid; j<N_; j+=512){
        float b0=0,b1=0,b2=0,b3=0,b4=0,b5=0,b6=0,b7=0;
        int qb = g_srowptr[j], qe = g_srowptr[j+1];
        for (int q=qb;q<qe;q++){
            int2 kp = g_sp[q];
            float a = __int_as_float(kp.y);
            float4 p0 = *(const float4*)&Psh[4*kp.x];
            float4 p1 = *(const float4*)&Psh[4*K_ + 4*kp.x];
            b0 += a*p0.x; b1 += a*p0.y; b2 += a*p0.z; b3 += a*p0.w;
            b4 += a*p1.x; b5 += a*p1.y; b6 += a*p1.z; b7 += a*p1.w;
        }
        adj[(size_t)(i0+0)*N_ + j]=b0; adj[(size_t)(i0+1)*N_ + j]=b1;
        adj[(size_t)(i0+2)*N_ + j]=b2; adj[(size_t)(i0+3)*N_ + j]=b3;
        adj[(size_t)(i0+4)*N_ + j]=b4; adj[(size_t)(i0+5)*N_ + j]=b5;
        adj[(size_t)(i0+6)*N_ + j]=b6; adj[(size_t)(i0+7)*N_ + j]=b7;
    }
}

// x_out[i,:] = sum over S row i: alpha*xp[k,:]  (warp per row, float4)
__global__ void k_xout(float* __restrict__ out){
    int i = blockIdx.x*8 + (threadIdx.x>>5);
    int lane = threadIdx.x & 31;
    const float4* xp4 = (const float4*)g_xp;
    float4 acc = make_float4(0,0,0,0);
    int beg=g_srowptr[i], end=g_srowptr[i+1];
    for (int q=beg;q<end;q++){
        int2 kp = g_sp[q];
        float a = __int_as_float(kp.y);
        float4 v = xp4[(size_t)kp.x*32 + lane];
        acc.x += a*v.x; acc.y += a*v.y; acc.z += a*v.z; acc.w += a*v.w;
    }
    ((float4*)out)[(size_t)i*32 + lane] = acc;
}

// ---------------- host ----------------
extern "C" void kernel_launch(void* const* d_in, const int* in_sizes, int n_in,
                              void* d_out, int out_size){
    const float* nodes = (const float*)d_in[0];
    const int*   edges = (const int*)d_in[1];
    const int* e0 = edges;
    const int* e1 = edges + E_;
    const float* w1 = (const float*)d_in[3];  const float* b1 = (const float*)d_in[4];
    const float* w2 = (const float*)d_in[5];  const float* b2 = (const float*)d_in[6];
    const float* w3 = (const float*)d_in[7];  const float* b3 = (const float*)d_in[8];
    const float* w4 = (const float*)d_in[9];  const float* b4 = (const float*)d_in[10];
    const float* w5 = (const float*)d_in[11]; const float* b5 = (const float*)d_in[12];
    const float* wq = (const float*)d_in[13]; const float* bq = (const float*)d_in[14];
    const float* att = (const float*)d_in[15];
    const float* lw1 = (const float*)d_in[16]; const float* lb1 = (const float*)d_in[17];
    const float* lw2 = (const float*)d_in[18]; const float* lw3 = (const float*)d_in[19];

    float* out = (float*)d_out;
    float* x2out = out;
    float* adj  = out + (size_t)N_*H_;

    float *A,*B,*C,*T; int *cnt,*ocnt,*rowptr,*orowptr,*scnt,*srowptr;
    cudaGetSymbolAddress((void**)&A, g_bufA);
    cudaGetSymbolAddress((void**)&B, g_bufB);
    cudaGetSymbolAddress((void**)&C, g_bufC);
    cudaGetSymbolAddress((void**)&T, g_bufT);
    cudaGetSymbolAddress((void**)&cnt, g_cnt);
    cudaGetSymbolAddress((void**)&ocnt, g_ocnt);
    cudaGetSymbolAddress((void**)&rowptr, g_rowptr);
    cudaGetSymbolAddress((void**)&orowptr, g_orowptr);
    cudaGetSymbolAddress((void**)&scnt, g_scnt);
    cudaGetSymbolAddress((void**)&srowptr, g_srowptr);

    const int TB = 256;
    const int MB = (M_ + TB - 1)/TB;

    // graph prep: dst-CSR + src-CSR with folded norms
    k_init0<<<(N_+TB-1)/TB, TB>>>();
    k_count<<<MB, TB>>>(e0, e1);
    k_dis<<<(N_+TB-1)/TB, TB>>>();
    k_scan8192<<<1,1024>>>(cnt, rowptr);
    k_scan8192<<<1,1024>>>(ocnt, orowptr);
    k_fill<<<MB, TB>>>(e0, e1);

    // encoder
    k_gemm<<<128,256>>>(nodes, w1, T);
    k_aggr<<<N_/8,256>>>(T, b1, A, 1);
    k_gemm<<<128,256>>>(A, w2, T);
    k_aggr<<<N_/8,256>>>(T, b2, B, 1);       // B = h

    // pooling
    k_segmax<<<N_/8,256>>>(B, A);
    k_gemm<<<128,256>>>(A, wq, T);
    k_dots<<<N_/8,256>>>(T, B, att, bq);
    k_softcx<<<N_,128>>>(B, C);              // C = cx, writes positional g_alpha
    k_le<<<N_/8,256>>>(C, lw1, lw2, lw3);
    k_fit<<<(N_+TB-1)/TB, TB>>>(lb1);
    k_topk<<<1,256>>>();
    k_xp<<<N_,128>>>(C);

    // S CSR (by source)
    k_scount<<<(N_+TB-1)/TB, TB>>>();
    k_scan8192<<<1,1024>>>(scnt, srowptr);
    k_zero_fill<<<(N_+TB-1)/TB, TB>>>();
    k_sfill<<<(N_+TB-1)/TB, TB>>>();

    // Ac rows via smem accumulation, then fused adj = (S Ac) S^T
    k_AcRow<<<K_, 256>>>();
    cudaFuncSetAttribute(k_adjF, cudaFuncAttributeMaxDynamicSharedMemorySize, PSH_WORDS*4);
    k_adjF<<<N_/8, 512, PSH_WORDS*4>>>(adj);

    // decoder
    k_xout<<<N_/8,256>>>(A);                 // A = x_out
    k_gemm<<<128,256>>>(A, w3, T);
    k_aggr<<<N_/8,256>>>(T, b3, B, 1);
    k_gemm<<<128,256>>>(B, w4, T);
    k_aggr<<<N_/8,256>>>(T, b4, A, 1);
    k_gemm<<<128,256>>>(A, w5, T);
    k_aggr<<<N_/8,256>>>(T, b5, x2out, 0);
}

// round 6
// speedup vs baseline: 1.7408x; 1.1578x over previous
#include <cuda_runtime.h>
#include <math.h>
#include <stdint.h>

#define N_ 8192
#define E_ 131072
#define M_ (E_ + N_)          // 139264 edges incl self loops
#define H_ 128
#define K_ 4096
#define WCAP_ 3000000

#define PSH_WORDS (8*K_)

// ---------------- device scratch ----------------
static __device__ float g_bufA[(size_t)N_*H_];
static __device__ float g_bufB[(size_t)N_*H_];
static __device__ float g_bufC[(size_t)N_*H_];
static __device__ float g_bufT[(size_t)N_*H_];
static __device__ float g_dis[N_];
static __device__ int   g_cnt[N_];
static __device__ int   g_ocnt[N_];
static __device__ int   g_fill[N_];
static __device__ int   g_ofill[N_];
static __device__ int   g_rowptr[N_+1];     // CSR by dst
static __device__ int   g_orowptr[N_+1];    // CSR by src
static __device__ int2  g_adj[M_];          // per dst-CSR pos: (src, norm bits)
static __device__ int   g_oadj[M_];         // per src-CSR pos: dst
static __device__ float g_alpha[M_];        // per dst-CSR pos
static __device__ float g_aq[N_];
static __device__ float g_ah[N_];
static __device__ float g_cl1[N_], g_cl2[N_], g_cl3[N_];
static __device__ float g_fit[N_];
static __device__ int   g_sel[N_];
static __device__ int   g_col[N_];
static __device__ int   g_ncol[K_];
static __device__ float g_xp[(size_t)K_*H_];
static __device__ int   g_scnt[N_];
static __device__ int   g_srowptr[N_+1];
static __device__ int2  g_sp[M_];            // packed (col k, alpha bits), CSR by src
static __device__ int   g_wcnt[N_];
static __device__ int   g_wrowptr[N_+1];
static __device__ int2  g_W[WCAP_];          // W = A*S rows (concat of S_j over out-edges)
static __device__ float g_Ac[(size_t)K_*K_];

// ---------------- helpers ----------------
__device__ __forceinline__ int esrc_f(const int* __restrict__ e0, int e){ return (e < E_) ? e0[e] : (e - E_); }
__device__ __forceinline__ int edst_f(const int* __restrict__ e1, int e){ return (e < E_) ? e1[e] : (e - E_); }

// ---------------- small utility kernels ----------------
__global__ void k_init0(){
    int i = blockIdx.x*blockDim.x + threadIdx.x;
    if (i < N_){ g_cnt[i]=0; g_ocnt[i]=0; g_fill[i]=0; g_ofill[i]=0; g_scnt[i]=0; }
}
__global__ void k_zeroN(int* __restrict__ p){
    int i = blockIdx.x*blockDim.x + threadIdx.x;
    if (i < N_) p[i]=0;
}
__global__ void k_count(const int* __restrict__ e0, const int* __restrict__ e1){
    int e = blockIdx.x*blockDim.x + threadIdx.x;
    if (e < M_){
        atomicAdd(&g_cnt[edst_f(e1,e)], 1);
        atomicAdd(&g_ocnt[esrc_f(e0,e)], 1);
    }
}
__global__ void k_dis(){
    int i = blockIdx.x*blockDim.x + threadIdx.x;
    if (i < N_) g_dis[i] = rsqrtf((float)g_cnt[i]);
}
// exclusive scan of exactly 8192 ints with 1024 threads (shfl-based)
__device__ __forceinline__ void scan8192_body(const int* __restrict__ in, int* __restrict__ out){
    __shared__ int wsum[32];
    int tid=threadIdx.x, lane=tid&31, wid=tid>>5;
    int4 a=((const int4*)in)[tid*2], b=((const int4*)in)[tid*2+1];
    int l[8]={a.x,a.y,a.z,a.w,b.x,b.y,b.z,b.w};
    int s=0;
    #pragma unroll
    for(int q=0;q<8;q++) s+=l[q];
    int inc=s;
    #pragma unroll
    for(int o=1;o<32;o<<=1){ int t=__shfl_up_sync(0xffffffffu,inc,o); if(lane>=o) inc+=t; }
    if(lane==31) wsum[wid]=inc;
    __syncthreads();
    if (wid==0){
        int v = wsum[lane];
        #pragma unroll
        for(int o=1;o<32;o<<=1){ int t=__shfl_up_sync(0xffffffffu,v,o); if(lane>=o) v+=t; }
        wsum[lane]=v;
    }
    __syncthreads();
    int r = inc - s + (wid? wsum[wid-1]:0);
    int4 o1,o2;
    o1.x=r; r+=l[0]; o1.y=r; r+=l[1]; o1.z=r; r+=l[2]; o1.w=r; r+=l[3];
    o2.x=r; r+=l[4]; o2.y=r; r+=l[5]; o2.z=r; r+=l[6]; o2.w=r; r+=l[7];
    ((int4*)out)[tid*2]=o1; ((int4*)out)[tid*2+1]=o2;
    if (tid==1023) out[8192]=r;
}
__global__ void k_scan8192(const int* __restrict__ in, int* __restrict__ out){
    scan8192_body(in, out);
}
__global__ void k_scan2(){
    if (blockIdx.x == 0) scan8192_body(g_cnt, g_rowptr);
    else                 scan8192_body(g_ocnt, g_orowptr);
}
// build positional adjacency with folded norm
__global__ void k_fill(const int* __restrict__ e0, const int* __restrict__ e1){
    int e = blockIdx.x*blockDim.x + threadIdx.x;
    if (e < M_){
        int s = esrc_f(e0,e);
        int d = edst_f(e1,e);
        float nm = g_dis[s]*g_dis[d];
        int pos = g_rowptr[d] + atomicAdd(&g_fill[d],1);
        g_adj[pos] = make_int2(s, __float_as_int(nm));
        int opos = g_orowptr[s] + atomicAdd(&g_ofill[s],1);
        g_oadj[opos] = d;
    }
}

// ---------------- 8192x128 @ 128x128 GEMM ----------------
__global__ void k_gemm(const float* __restrict__ x, const float* __restrict__ w, float* __restrict__ y){
    __shared__ __align__(16) float xs[128*64];   // [kk][r]
    int r0 = blockIdx.x*64;
    int tid = threadIdx.x;
    for (int idx=tid; idx<64*128; idx+=256){
        int r = idx >> 7;
        int kk = idx & 127;
        xs[kk*64 + r] = x[(size_t)(r0+r)*128 + kk];
    }
    __syncthreads();
    int cg = tid & 31;
    int rg = tid >> 5;
    float acc[8][4];
    #pragma unroll
    for(int r=0;r<8;r++){ acc[r][0]=0.f;acc[r][1]=0.f;acc[r][2]=0.f;acc[r][3]=0.f; }
    #pragma unroll 4
    for(int kk=0;kk<128;kk++){
        float4 wv = *(const float4*)(w + kk*128 + cg*4);
        float4 x0 = *(const float4*)(xs + kk*64 + rg*8);
        float4 x1 = *(const float4*)(xs + kk*64 + rg*8 + 4);
        float xv[8] = {x0.x,x0.y,x0.z,x0.w,x1.x,x1.y,x1.z,x1.w};
        #pragma unroll
        for(int r=0;r<8;r++){
            acc[r][0] += xv[r]*wv.x; acc[r][1] += xv[r]*wv.y;
            acc[r][2] += xv[r]*wv.z; acc[r][3] += xv[r]*wv.w;
        }
    }
    #pragma unroll
    for(int r=0;r<8;r++){
        float4 o = make_float4(acc[r][0],acc[r][1],acc[r][2],acc[r][3]);
        *(float4*)(y + (size_t)(r0+rg*8+r)*128 + cg*4) = o;
    }
}

// ---------------- GCN aggregation: warp per dst, float4 lanes ----------------
__global__ void k_aggr(const float* __restrict__ y, const float* __restrict__ b,
                       float* __restrict__ out, int dotanh){
    int d = blockIdx.x*8 + (threadIdx.x>>5);
    int lane = threadIdx.x & 31;
    const float4* y4 = (const float4*)y;
    float4 acc = ((const float4*)b)[lane];
    int beg = g_rowptr[d], end = g_rowptr[d+1];
    int p = beg;
    for (; p+1 < end; p += 2){
        int2 a0 = g_adj[p], a1 = g_adj[p+1];
        float n0 = __int_as_float(a0.y), n1 = __int_as_float(a1.y);
        float4 v0 = y4[(size_t)a0.x*32 + lane];
        float4 v1 = y4[(size_t)a1.x*32 + lane];
        acc.x += n0*v0.x + n1*v1.x;
        acc.y += n0*v0.y + n1*v1.y;
        acc.z += n0*v0.z + n1*v1.z;
        acc.w += n0*v0.w + n1*v1.w;
    }
    if (p < end){
        int2 a0 = g_adj[p];
        float n0 = __int_as_float(a0.y);
        float4 v0 = y4[(size_t)a0.x*32 + lane];
        acc.x += n0*v0.x; acc.y += n0*v0.y; acc.z += n0*v0.z; acc.w += n0*v0.w;
    }
    if (dotanh){
        acc.x = tanhf(acc.x); acc.y = tanhf(acc.y);
        acc.z = tanhf(acc.z); acc.w = tanhf(acc.w);
    }
    ((float4*)out)[(size_t)d*32 + lane] = acc;
}

__global__ void k_segmax(const float* __restrict__ h, float* __restrict__ out){
    int d = blockIdx.x*8 + (threadIdx.x>>5);
    int lane = threadIdx.x & 31;
    const float4* h4 = (const float4*)h;
    float4 acc = make_float4(-INFINITY,-INFINITY,-INFINITY,-INFINITY);
    int beg = g_rowptr[d], end = g_rowptr[d+1];
    for (int p=beg; p<end; p++){
        float4 v = h4[(size_t)g_adj[p].x*32 + lane];
        acc.x = fmaxf(acc.x,v.x); acc.y = fmaxf(acc.y,v.y);
        acc.z = fmaxf(acc.z,v.z); acc.w = fmaxf(acc.w,v.w);
    }
    ((float4*)out)[(size_t)d*32 + lane] = acc;
}

__global__ void k_dots(const float* __restrict__ xq, const float* __restrict__ h,
                       const float* __restrict__ att, const float* __restrict__ bq){
    int node = blockIdx.x*8 + (threadIdx.x>>5);
    int lane = threadIdx.x & 31;
    const float4* xq4 = (const float4*)xq;
    const float4* h4  = (const float4*)h;
    const float4* at4 = (const float4*)att;
    const float4* bq4 = (const float4*)bq;
    float4 a1 = at4[lane], a2 = at4[32+lane];
    float4 xv = xq4[(size_t)node*32+lane], bv = bq4[lane], hv = h4[(size_t)node*32+lane];
    float s1 = a1.x*(xv.x+bv.x) + a1.y*(xv.y+bv.y) + a1.z*(xv.z+bv.z) + a1.w*(xv.w+bv.w);
    float s2 = a2.x*hv.x + a2.y*hv.y + a2.z*hv.z + a2.w*hv.w;
    #pragma unroll
    for (int o=16;o;o>>=1){ s1 += __shfl_down_sync(0xffffffffu,s1,o); s2 += __shfl_down_sync(0xffffffffu,s2,o); }
    if (!lane){ g_aq[node]=s1; g_ah[node]=s2; }
}

// per-dst softmax over in-edges (positional alpha) + cluster rep cx
__global__ void k_softcx(const float* __restrict__ h, float* __restrict__ cx){
    __shared__ float red[128];
    __shared__ float cache[1024];
    __shared__ int   scache[1024];
    int d = blockIdx.x, t = threadIdx.x;
    int beg = g_rowptr[d], end = g_rowptr[d+1];
    float aqd = g_aq[d];
    float mx = -INFINITY;
    for (int s=beg+t; s<end; s+=128){
        int src = g_adj[s].x;
        float sc = aqd + g_ah[src];
        sc = sc > 0.f ? sc : 0.2f*sc;
        if (s-beg < 1024){ cache[s-beg] = sc; scache[s-beg] = src; }
        mx = fmaxf(mx, sc);
    }
    red[t]=mx; __syncthreads();
    for (int o=64;o;o>>=1){ if(t<o) red[t]=fmaxf(red[t],red[t+o]); __syncthreads(); }
    mx = red[0]; __syncthreads();
    float sm = 0.f;
    for (int s=beg+t; s<end; s+=128){
        float sc;
        if (s-beg < 1024) sc = cache[s-beg];
        else { float v = aqd + g_ah[g_adj[s].x]; sc = v>0.f? v : 0.2f*v; }
        float ee = __expf(sc - mx);
        if (s-beg < 1024) cache[s-beg] = ee;
        sm += ee;
    }
    red[t]=sm; __syncthreads();
    for (int o=64;o;o>>=1){ if(t<o) red[t]+=red[t+o]; __syncthreads(); }
    float inv = 1.f/red[0];
    for (int s=beg+t; s<end; s+=128){
        float ee;
        if (s-beg < 1024) ee = cache[s-beg];
        else { float v = aqd + g_ah[g_adj[s].x]; v = v>0.f? v:0.2f*v; ee = __expf(v-mx); }
        float a = ee*inv;
        g_alpha[s] = a;
        if (s-beg < 1024) cache[s-beg] = a;
    }
    __syncthreads();
    float acc = 0.f;
    for (int s=beg; s<end; s++){
        float a; int src;
        if (s-beg < 1024){ a = cache[s-beg]; src = scache[s-beg]; }
        else { a = g_alpha[s]; src = g_adj[s].x; }
        acc += a * h[(size_t)src*128 + t];
    }
    cx[(size_t)d*128 + t] = acc;
}

__global__ void k_le(const float* __restrict__ cx, const float* __restrict__ lw1,
                     const float* __restrict__ lw2, const float* __restrict__ lw3){
    int node = blockIdx.x*8 + (threadIdx.x>>5);
    int lane = threadIdx.x & 31;
    const float4* c4 = (const float4*)cx;
    const float4* w14 = (const float4*)lw1;
    const float4* w24 = (const float4*)lw2;
    const float4* w34 = (const float4*)lw3;
    float4 v = c4[(size_t)node*32+lane];
    float4 w1v = w14[lane], w2v = w24[lane], w3v = w34[lane];
    float s1 = v.x*w1v.x + v.y*w1v.y + v.z*w1v.z + v.w*w1v.w;
    float s2 = v.x*w2v.x + v.y*w2v.y + v.z*w2v.z + v.w*w2v.w;
    float s3 = v.x*w3v.x + v.y*w3v.y + v.z*w3v.z + v.w*w3v.w;
    #pragma unroll
    for (int o=16;o;o>>=1){
        s1 += __shfl_down_sync(0xffffffffu,s1,o);
        s2 += __shfl_down_sync(0xffffffffu,s2,o);
        s3 += __shfl_down_sync(0xffffffffu,s3,o);
    }
    if (!lane){ g_cl1[node]=s1; g_cl2[node]=s2; g_cl3[node]=s3; }
}
__global__ void k_fit(const float* __restrict__ lb1){
    int d = blockIdx.x*blockDim.x + threadIdx.x;
    if (d >= N_) return;
    int beg=g_rowptr[d], end=g_rowptr[d+1];
    float s = 0.f;
    for (int q=beg;q<end;q++) s += g_cl3[g_adj[q].x];
    float aggr = (float)(end-beg)*g_cl2[d] - s;
    float z = g_cl1[d] + lb1[0] + aggr;
    g_fit[d] = 1.f/(1.f + __expf(-z));
}

// ---------------- top-K via 4x8-bit histogram radix select ----------------
__global__ void k_topk(){
    __shared__ int hist[256];
    __shared__ int wred[8];
    __shared__ unsigned s_pref;
    __shared__ int s_need;
    int tid=threadIdx.x, lane=tid&31, wid=tid>>5;
    if (tid==0){ s_pref=0u; s_need=K_; }
    unsigned keys[32];
    #pragma unroll
    for (int q=0;q<32;q++){
        unsigned u=__float_as_uint(g_fit[tid*32+q]);
        keys[q] = (u & 0x80000000u) ? ~u : (u | 0x80000000u);
    }
    __syncthreads();
    for (int round=0; round<4; round++){
        int shift = 24 - 8*round;
        hist[tid]=0;
        __syncthreads();
        unsigned pref = s_pref;
        #pragma unroll
        for (int q=0;q<32;q++){
            unsigned k = keys[q];
            bool match = (round==0) || ((k >> (shift+8)) == (pref >> (shift+8)));
            if (match) atomicAdd(&hist[(k>>shift)&0xFFu], 1);
        }
        __syncthreads();
        int mine = hist[255-tid];
        int v = mine;
        #pragma unroll
        for (int o=1;o<32;o<<=1){ int t2=__shfl_up_sync(0xffffffffu,v,o); if(lane>=o) v+=t2; }
        if (lane==31) wred[wid]=v;
        __syncthreads();
        int woff=0;
        #pragma unroll
        for (int w=0;w<8;w++) if (w<wid) woff+=wred[w];
        v += woff;
        int need0 = s_need;
        int vex = v - mine;
        if (v >= need0 && vex < need0){
            s_pref = s_pref | ((unsigned)(255-tid) << shift);
            s_need = need0 - vex;
        }
        __syncthreads();
    }
    unsigned thr = s_pref;
    int need = s_need;
    int tcnt=0;
    #pragma unroll
    for (int q=0;q<32;q++) tcnt += (keys[q]==thr);
    int v=tcnt;
    #pragma unroll
    for (int o=1;o<32;o<<=1){ int t2=__shfl_up_sync(0xffffffffu,v,o); if(lane>=o) v+=t2; }
    if (lane==31) wred[wid]=v;
    __syncthreads();
    int woff=0;
    #pragma unroll
    for (int w=0;w<8;w++) if (w<wid) woff+=wred[w];
    int rank = v - tcnt + woff;
    int scnt=0;
    int selq[32];
    #pragma unroll
    for (int q=0;q<32;q++){
        unsigned k=keys[q];
        bool eq = (k==thr);
        int s = (k>thr) || (eq && rank < need);
        if (eq) rank++;
        selq[q]=s;
        g_sel[tid*32+q]=s;
        scnt+=s;
    }
    __syncthreads();
    v=scnt;
    #pragma unroll
    for (int o=1;o<32;o<<=1){ int t2=__shfl_up_sync(0xffffffffu,v,o); if(lane>=o) v+=t2; }
    if (lane==31) wred[wid]=v;
    __syncthreads();
    woff=0;
    #pragma unroll
    for (int w=0;w<8;w++) if (w<wid) woff+=wred[w];
    int base = v - scnt + woff;
    #pragma unroll
    for (int q=0;q<32;q++){
        int i = tid*32+q;
        if (selq[q]){ g_col[i]=base; g_ncol[base]=i; base++; }
        else g_col[i]=-1;
    }
}

__global__ void k_xp(const float* __restrict__ cx){
    int i = blockIdx.x, t = threadIdx.x;
    if (!g_sel[i]) return;
    g_xp[(size_t)g_col[i]*128 + t] = cx[(size_t)i*128 + t] * g_fit[i];
}

// ---------------- S CSR (by source): count + fill from dst rows ----------------
__global__ void k_scount(){
    int d = blockIdx.x*blockDim.x + threadIdx.x;
    if (d >= N_ || !g_sel[d]) return;
    int beg=g_rowptr[d], end=g_rowptr[d+1];
    for (int p=beg;p<end;p++) atomicAdd(&g_scnt[g_adj[p].x], 1);
}
__global__ void k_sfill(){
    int d = blockIdx.x*blockDim.x + threadIdx.x;
    if (d >= N_ || !g_sel[d]) return;
    int colk = g_col[d];
    int beg=g_rowptr[d], end=g_rowptr[d+1];
    for (int p=beg;p<end;p++){
        int s = g_adj[p].x;
        int pos = g_srowptr[s] + atomicAdd(&g_fill[s],1);
        g_sp[pos] = make_int2(colk, __float_as_int(g_alpha[p]));
    }
}

// ---------------- W = A*S (sparse rows): count, fill ----------------
__global__ void k_wcount(){
    int s = blockIdx.x*blockDim.x + threadIdx.x;
    if (s >= N_) return;
    int ob=g_orowptr[s], oe=g_orowptr[s+1];
    int total=0;
    for (int f=ob;f<oe;f++){
        int j = g_oadj[f];
        total += g_srowptr[j+1]-g_srowptr[j];
    }
    g_wcnt[s]=total;
}
// warp per source: copy S_j lists into W row
__global__ void k_wfill(){
    int s = blockIdx.x*8 + (threadIdx.x>>5);
    int lane = threadIdx.x & 31;
    int wpos = g_wrowptr[s];
    int ob=g_orowptr[s], oe=g_orowptr[s+1];
    for (int f=ob;f<oe;f++){
        int j = g_oadj[f];
        int sb=g_srowptr[j], len=g_srowptr[j+1]-sb;
        for (int q=lane;q<len;q+=32) g_W[wpos+q]=g_sp[sb+q];
        wpos += len;
    }
}

// ---------------- Ac row gather with smem accumulator (flat W rows) ----------------
__global__ void k_AcRow(){
    __shared__ float acc[K_];
    int k = blockIdx.x, tid = threadIdx.x;
    int lane = tid & 31, w = tid >> 5, nw = blockDim.x >> 5;
    for (int m=tid; m<K_; m+=blockDim.x) acc[m]=0.f;
    __syncthreads();
    int d = g_ncol[k];
    int ib = g_rowptr[d], ie = g_rowptr[d+1];
    for (int p=ib+w; p<ie; p+=nw){
        int s = g_adj[p].x;
        float ae = g_alpha[p];
        int wb = g_wrowptr[s], we = g_wrowptr[s+1];
        for (int q=wb+lane; q<we; q+=32){
            int2 e = g_W[q];
            atomicAdd(&acc[e.x], ae*__int_as_float(e.y));
        }
    }
    __syncthreads();
    float* orow = &g_Ac[(size_t)k*K_];
    for (int m=tid; m<K_; m+=blockDim.x) orow[m]=acc[m];
}

// ---------------- fused: build 8 P-rows (registers->smem), then adj = P S^T ----------------
// 1024 threads; Psh layout: lo half rows 0..3, hi half rows 4..7; half[16*g + 4*u + rr]
__global__ void k_adjF(float* __restrict__ adj){
    extern __shared__ __align__(16) float Psh[];
    int i0 = blockIdx.x*8, tid = threadIdx.x;
    const float4* Ac4 = (const float4*)g_Ac;
    #pragma unroll 1
    for (int r=0;r<8;r++){
        float4 a0 = make_float4(0,0,0,0);
        int qb=g_srowptr[i0+r], qe=g_srowptr[i0+r+1];
        for (int q=qb;q<qe;q++){
            int2 kp = g_sp[q];
            float a = __int_as_float(kp.y);
            float4 v0 = Ac4[(size_t)kp.x*(K_/4) + tid];
            a0.x += a*v0.x; a0.y += a*v0.y; a0.z += a*v0.z; a0.w += a*v0.w;
        }
        float* half = Psh + ((r>=4) ? 4*K_ : 0);
        int rr = r & 3;
        half[16*tid + 0 + rr] = a0.x; half[16*tid + 4 + rr] = a0.y;
        half[16*tid + 8 + rr] = a0.z; half[16*tid +12 + rr] = a0.w;
    }
    __syncthreads();
    for (int j=tid; j<N_; j+=1024){
        float b0=0,b1=0,b2=0,b3=0,b4=0,b5=0,b6=0,b7=0;
        int qb = g_srowptr[j], qe = g_srowptr[j+1];
        for (int q=qb;q<qe;q++){
            int2 kp = g_sp[q];
            float a = __int_as_float(kp.y);
            float4 p0 = *(const float4*)&Psh[4*kp.x];
            float4 p1 = *(const float4*)&Psh[4*K_ + 4*kp.x];
            b0 += a*p0.x; b1 += a*p0.y; b2 += a*p0.z; b3 += a*p0.w;
            b4 += a*p1.x; b5 += a*p1.y; b6 += a*p1.z; b7 += a*p1.w;
        }
        adj[(size_t)(i0+0)*N_ + j]=b0; adj[(size_t)(i0+1)*N_ + j]=b1;
        adj[(size_t)(i0+2)*N_ + j]=b2; adj[(size_t)(i0+3)*N_ + j]=b3;
        adj[(size_t)(i0+4)*N_ + j]=b4; adj[(size_t)(i0+5)*N_ + j]=b5;
        adj[(size_t)(i0+6)*N_ + j]=b6; adj[(size_t)(i0+7)*N_ + j]=b7;
    }
}

// x_out[i,:] = sum over S row i: alpha*xp[k,:]  (warp per row, float4)
__global__ void k_xout(float* __restrict__ out){
    int i = blockIdx.x*8 + (threadIdx.x>>5);
    int lane = threadIdx.x & 31;
    const float4* xp4 = (const float4*)g_xp;
    float4 acc = make_float4(0,0,0,0);
    int beg=g_srowptr[i], end=g_srowptr[i+1];
    for (int q=beg;q<end;q++){
        int2 kp = g_sp[q];
        float a = __int_as_float(kp.y);
        float4 v = xp4[(size_t)kp.x*32 + lane];
        acc.x += a*v.x; acc.y += a*v.y; acc.z += a*v.z; acc.w += a*v.w;
    }
    ((float4*)out)[(size_t)i*32 + lane] = acc;
}

// ---------------- host ----------------
extern "C" void kernel_launch(void* const* d_in, const int* in_sizes, int n_in,
                              void* d_out, int out_size){
    const float* nodes = (const float*)d_in[0];
    const int*   edges = (const int*)d_in[1];
    const int* e0 = edges;
    const int* e1 = edges + E_;
    const float* w1 = (const float*)d_in[3];  const float* b1 = (const float*)d_in[4];
    const float* w2 = (const float*)d_in[5];  const float* b2 = (const float*)d_in[6];
    const float* w3 = (const float*)d_in[7];  const float* b3 = (const float*)d_in[8];
    const float* w4 = (const float*)d_in[9];  const float* b4 = (const float*)d_in[10];
    const float* w5 = (const float*)d_in[11]; const float* b5 = (const float*)d_in[12];
    const float* wq = (const float*)d_in[13]; const float* bq = (const float*)d_in[14];
    const float* att = (const float*)d_in[15];
    const float* lw1 = (const float*)d_in[16]; const float* lb1 = (const float*)d_in[17];
    const float* lw2 = (const float*)d_in[18]; const float* lw3 = (const float*)d_in[19];

    float* out = (float*)d_out;
    float* x2out = out;
    float* adj  = out + (size_t)N_*H_;

    float *A,*B,*C,*T; int *scnt,*srowptr,*wcnt,*wrowptr,*fill;
    cudaGetSymbolAddress((void**)&A, g_bufA);
    cudaGetSymbolAddress((void**)&B, g_bufB);
    cudaGetSymbolAddress((void**)&C, g_bufC);
    cudaGetSymbolAddress((void**)&T, g_bufT);
    cudaGetSymbolAddress((void**)&scnt, g_scnt);
    cudaGetSymbolAddress((void**)&srowptr, g_srowptr);
    cudaGetSymbolAddress((void**)&wcnt, g_wcnt);
    cudaGetSymbolAddress((void**)&wrowptr, g_wrowptr);
    cudaGetSymbolAddress((void**)&fill, g_fill);

    const int TB = 256;
    const int MB = (M_ + TB - 1)/TB;
    const int NB = (N_ + TB - 1)/TB;

    // graph prep: dst-CSR + src-CSR with folded norms
    k_init0<<<NB, TB>>>();
    k_count<<<MB, TB>>>(e0, e1);
    k_dis<<<NB, TB>>>();
    k_scan2<<<2,1024>>>();
    k_fill<<<MB, TB>>>(e0, e1);

    // encoder
    k_gemm<<<128,256>>>(nodes, w1, T);
    k_aggr<<<N_/8,256>>>(T, b1, A, 1);
    k_gemm<<<128,256>>>(A, w2, T);
    k_aggr<<<N_/8,256>>>(T, b2, B, 1);       // B = h

    // pooling
    k_segmax<<<N_/8,256>>>(B, A);
    k_gemm<<<128,256>>>(A, wq, T);
    k_dots<<<N_/8,256>>>(T, B, att, bq);
    k_softcx<<<N_,128>>>(B, C);              // C = cx, writes positional g_alpha
    k_le<<<N_/8,256>>>(C, lw1, lw2, lw3);
    k_fit<<<NB, TB>>>(lb1);
    k_topk<<<1,256>>>();
    k_xp<<<N_,128>>>(C);

    // S CSR (by source)
    k_scount<<<NB, TB>>>();
    k_scan8192<<<1,1024>>>(scnt, srowptr);
    k_zeroN<<<NB, TB>>>(fill);
    k_sfill<<<NB, TB>>>();

    // W = A*S sparse rows
    k_wcount<<<NB, TB>>>();
    k_scan8192<<<1,1024>>>(wcnt, wrowptr);
    k_wfill<<<N_/8, 256>>>();

    // Ac rows via smem accumulation over flat W rows, then fused adj = (S Ac) S^T
    k_AcRow<<<K_, 256>>>();
    cudaFuncSetAttribute(k_adjF, cudaFuncAttributeMaxDynamicSharedMemorySize, PSH_WORDS*4);
    k_adjF<<<N_/8, 1024, PSH_WORDS*4>>>(adj);

    // decoder
    k_xout<<<N_/8,256>>>(A);                 // A = x_out
    k_gemm<<<128,256>>>(A, w3, T);
    k_aggr<<<N_/8,256>>>(T, b3, B, 1);
    k_gemm<<<128,256>>>(B, w4, T);
    k_aggr<<<N_/8,256>>>(T, b4, A, 1);
    k_gemm<<<128,256>>>(A, w5, T);
    k_aggr<<<N_/8,256>>>(T, b5, x2out, 0);
}

// round 7
// speedup vs baseline: 1.9390x; 1.1139x over previous
#include <cuda_runtime.h>
#include <math.h>
#include <stdint.h>

#define N_ 8192
#define E_ 131072
#define M_ (E_ + N_)          // 139264 edges incl self loops
#define H_ 128
#define K_ 4096
#define WCAP_ 3000000

#define PSH_WORDS (8*K_)

// ---------------- device scratch ----------------
static __device__ float g_bufA[(size_t)N_*H_];
static __device__ float g_bufB[(size_t)N_*H_];
static __device__ float g_bufC[(size_t)N_*H_];
static __device__ float g_bufT[(size_t)N_*H_];
static __device__ int   g_cnt[N_];
static __device__ int   g_ocnt[N_];
static __device__ int   g_fill[N_];
static __device__ int   g_ofill[N_];
static __device__ int   g_rowptr[N_+1];     // CSR by dst
static __device__ int   g_orowptr[N_+1];    // CSR by src
static __device__ int2  g_adj[M_];          // per dst-CSR pos: (src, norm bits)
static __device__ int   g_oadj[M_];         // per src-CSR pos: dst
static __device__ float g_alpha[M_];        // per dst-CSR pos
static __device__ float g_aq[N_];
static __device__ float g_ah[N_];
static __device__ float g_cl1[N_], g_cl2[N_], g_cl3[N_];
static __device__ float g_fit[N_];
static __device__ int   g_sel[N_];
static __device__ int   g_col[N_];
static __device__ int   g_ncol[K_];
static __device__ float g_xp[(size_t)K_*H_];
static __device__ int   g_scnt[N_];
static __device__ int   g_srowptr[N_+1];
static __device__ int2  g_sp[M_];            // packed (col k, alpha bits), CSR by src
static __device__ int   g_wcnt[N_];
static __device__ int   g_wrowptr[N_+1];
static __device__ int2  g_W[WCAP_];          // W = A*S rows
static __device__ float g_Ac[(size_t)K_*K_];

// ---------------- helpers ----------------
__device__ __forceinline__ int esrc_f(const int* __restrict__ e0, int e){ return (e < E_) ? e0[e] : (e - E_); }
__device__ __forceinline__ int edst_f(const int* __restrict__ e1, int e){ return (e < E_) ? e1[e] : (e - E_); }

// ---------------- small utility kernels ----------------
__global__ void k_init0(){
    int i = blockIdx.x*blockDim.x + threadIdx.x;
    if (i < N_){ g_cnt[i]=0; g_ocnt[i]=0; g_fill[i]=0; g_ofill[i]=0; g_scnt[i]=0; }
}
__global__ void k_zeroN(int* __restrict__ p){
    int i = blockIdx.x*blockDim.x + threadIdx.x;
    if (i < N_) p[i]=0;
}
__global__ void k_count(const int* __restrict__ e0, const int* __restrict__ e1){
    int e = blockIdx.x*blockDim.x + threadIdx.x;
    if (e < M_){
        atomicAdd(&g_cnt[edst_f(e1,e)], 1);
        atomicAdd(&g_ocnt[esrc_f(e0,e)], 1);
    }
}
// exclusive scan of exactly 8192 ints with 1024 threads (shfl-based)
__device__ __forceinline__ void scan8192_body(const int* __restrict__ in, int* __restrict__ out){
    __shared__ int wsum[32];
    int tid=threadIdx.x, lane=tid&31, wid=tid>>5;
    int4 a=((const int4*)in)[tid*2], b=((const int4*)in)[tid*2+1];
    int l[8]={a.x,a.y,a.z,a.w,b.x,b.y,b.z,b.w};
    int s=0;
    #pragma unroll
    for(int q=0;q<8;q++) s+=l[q];
    int inc=s;
    #pragma unroll
    for(int o=1;o<32;o<<=1){ int t=__shfl_up_sync(0xffffffffu,inc,o); if(lane>=o) inc+=t; }
    if(lane==31) wsum[wid]=inc;
    __syncthreads();
    if (wid==0){
        int v = wsum[lane];
        #pragma unroll
        for(int o=1;o<32;o<<=1){ int t=__shfl_up_sync(0xffffffffu,v,o); if(lane>=o) v+=t; }
        wsum[lane]=v;
    }
    __syncthreads();
    int r = inc - s + (wid? wsum[wid-1]:0);
    int4 o1,o2;
    o1.x=r; r+=l[0]; o1.y=r; r+=l[1]; o1.z=r; r+=l[2]; o1.w=r; r+=l[3];
    o2.x=r; r+=l[4]; o2.y=r; r+=l[5]; o2.z=r; r+=l[6]; o2.w=r; r+=l[7];
    ((int4*)out)[tid*2]=o1; ((int4*)out)[tid*2+1]=o2;
    if (tid==1023) out[8192]=r;
}
__global__ void k_scan8192(const int* __restrict__ in, int* __restrict__ out){
    scan8192_body(in, out);
}
__global__ void k_scan2(){
    if (blockIdx.x == 0) scan8192_body(g_cnt, g_rowptr);
    else                 scan8192_body(g_ocnt, g_orowptr);
}
// build positional adjacency with folded norm (dis computed inline)
__global__ void k_fill(const int* __restrict__ e0, const int* __restrict__ e1){
    int e = blockIdx.x*blockDim.x + threadIdx.x;
    if (e < M_){
        int s = esrc_f(e0,e);
        int d = edst_f(e1,e);
        float nm = rsqrtf((float)g_cnt[s]) * rsqrtf((float)g_cnt[d]);
        int pos = g_rowptr[d] + atomicAdd(&g_fill[d],1);
        g_adj[pos] = make_int2(s, __float_as_int(nm));
        int opos = g_orowptr[s] + atomicAdd(&g_ofill[s],1);
        g_oadj[opos] = d;
    }
}

// ---------------- 8192x128 @ 128x128 GEMM ----------------
__global__ void k_gemm(const float* __restrict__ x, const float* __restrict__ w, float* __restrict__ y){
    __shared__ __align__(16) float xs[128*64];   // [kk][r]
    int r0 = blockIdx.x*64;
    int tid = threadIdx.x;
    for (int idx=tid; idx<64*128; idx+=256){
        int r = idx >> 7;
        int kk = idx & 127;
        xs[kk*64 + r] = x[(size_t)(r0+r)*128 + kk];
    }
    __syncthreads();
    int cg = tid & 31;
    int rg = tid >> 5;
    float acc[8][4];
    #pragma unroll
    for(int r=0;r<8;r++){ acc[r][0]=0.f;acc[r][1]=0.f;acc[r][2]=0.f;acc[r][3]=0.f; }
    #pragma unroll 4
    for(int kk=0;kk<128;kk++){
        float4 wv = *(const float4*)(w + kk*128 + cg*4);
        float4 x0 = *(const float4*)(xs + kk*64 + rg*8);
        float4 x1 = *(const float4*)(xs + kk*64 + rg*8 + 4);
        float xv[8] = {x0.x,x0.y,x0.z,x0.w,x1.x,x1.y,x1.z,x1.w};
        #pragma unroll
        for(int r=0;r<8;r++){
            acc[r][0] += xv[r]*wv.x; acc[r][1] += xv[r]*wv.y;
            acc[r][2] += xv[r]*wv.z; acc[r][3] += xv[r]*wv.w;
        }
    }
    #pragma unroll
    for(int r=0;r<8;r++){
        float4 o = make_float4(acc[r][0],acc[r][1],acc[r][2],acc[r][3]);
        *(float4*)(y + (size_t)(r0+rg*8+r)*128 + cg*4) = o;
    }
}

// ---------------- GCN aggregation: warp per dst, float4 lanes ----------------
__global__ void k_aggr(const float* __restrict__ y, const float* __restrict__ b,
                       float* __restrict__ out, int dotanh){
    int d = blockIdx.x*8 + (threadIdx.x>>5);
    int lane = threadIdx.x & 31;
    const float4* y4 = (const float4*)y;
    float4 acc = ((const float4*)b)[lane];
    int beg = g_rowptr[d], end = g_rowptr[d+1];
    int p = beg;
    for (; p+1 < end; p += 2){
        int2 a0 = g_adj[p], a1 = g_adj[p+1];
        float n0 = __int_as_float(a0.y), n1 = __int_as_float(a1.y);
        float4 v0 = y4[(size_t)a0.x*32 + lane];
        float4 v1 = y4[(size_t)a1.x*32 + lane];
        acc.x += n0*v0.x + n1*v1.x;
        acc.y += n0*v0.y + n1*v1.y;
        acc.z += n0*v0.z + n1*v1.z;
        acc.w += n0*v0.w + n1*v1.w;
    }
    if (p < end){
        int2 a0 = g_adj[p];
        float n0 = __int_as_float(a0.y);
        float4 v0 = y4[(size_t)a0.x*32 + lane];
        acc.x += n0*v0.x; acc.y += n0*v0.y; acc.z += n0*v0.z; acc.w += n0*v0.w;
    }
    if (dotanh){
        acc.x = tanhf(acc.x); acc.y = tanhf(acc.y);
        acc.z = tanhf(acc.z); acc.w = tanhf(acc.w);
    }
    ((float4*)out)[(size_t)d*32 + lane] = acc;
}

__global__ void k_segmax(const float* __restrict__ h, float* __restrict__ out){
    int d = blockIdx.x*8 + (threadIdx.x>>5);
    int lane = threadIdx.x & 31;
    const float4* h4 = (const float4*)h;
    float4 acc = make_float4(-INFINITY,-INFINITY,-INFINITY,-INFINITY);
    int beg = g_rowptr[d], end = g_rowptr[d+1];
    for (int p=beg; p<end; p++){
        float4 v = h4[(size_t)g_adj[p].x*32 + lane];
        acc.x = fmaxf(acc.x,v.x); acc.y = fmaxf(acc.y,v.y);
        acc.z = fmaxf(acc.z,v.z); acc.w = fmaxf(acc.w,v.w);
    }
    ((float4*)out)[(size_t)d*32 + lane] = acc;
}

__global__ void k_dots(const float* __restrict__ xq, const float* __restrict__ h,
                       const float* __restrict__ att, const float* __restrict__ bq){
    int node = blockIdx.x*8 + (threadIdx.x>>5);
    int lane = threadIdx.x & 31;
    const float4* xq4 = (const float4*)xq;
    const float4* h4  = (const float4*)h;
    const float4* at4 = (const float4*)att;
    const float4* bq4 = (const float4*)bq;
    float4 a1 = at4[lane], a2 = at4[32+lane];
    float4 xv = xq4[(size_t)node*32+lane], bv = bq4[lane], hv = h4[(size_t)node*32+lane];
    float s1 = a1.x*(xv.x+bv.x) + a1.y*(xv.y+bv.y) + a1.z*(xv.z+bv.z) + a1.w*(xv.w+bv.w);
    float s2 = a2.x*hv.x + a2.y*hv.y + a2.z*hv.z + a2.w*hv.w;
    #pragma unroll
    for (int o=16;o;o>>=1){ s1 += __shfl_down_sync(0xffffffffu,s1,o); s2 += __shfl_down_sync(0xffffffffu,s2,o); }
    if (!lane){ g_aq[node]=s1; g_ah[node]=s2; }
}

// per-dst softmax over in-edges (positional alpha) + cluster rep cx
__global__ void k_softcx(const float* __restrict__ h, float* __restrict__ cx){
    __shared__ float red[128];
    __shared__ float cache[1024];
    __shared__ int   scache[1024];
    int d = blockIdx.x, t = threadIdx.x;
    int beg = g_rowptr[d], end = g_rowptr[d+1];
    float aqd = g_aq[d];
    float mx = -INFINITY;
    for (int s=beg+t; s<end; s+=128){
        int src = g_adj[s].x;
        float sc = aqd + g_ah[src];
        sc = sc > 0.f ? sc : 0.2f*sc;
        if (s-beg < 1024){ cache[s-beg] = sc; scache[s-beg] = src; }
        mx = fmaxf(mx, sc);
    }
    red[t]=mx; __syncthreads();
    for (int o=64;o;o>>=1){ if(t<o) red[t]=fmaxf(red[t],red[t+o]); __syncthreads(); }
    mx = red[0]; __syncthreads();
    float sm = 0.f;
    for (int s=beg+t; s<end; s+=128){
        float sc;
        if (s-beg < 1024) sc = cache[s-beg];
        else { float v = aqd + g_ah[g_adj[s].x]; sc = v>0.f? v : 0.2f*v; }
        float ee = __expf(sc - mx);
        if (s-beg < 1024) cache[s-beg] = ee;
        sm += ee;
    }
    red[t]=sm; __syncthreads();
    for (int o=64;o;o>>=1){ if(t<o) red[t]+=red[t+o]; __syncthreads(); }
    float inv = 1.f/red[0];
    for (int s=beg+t; s<end; s+=128){
        float ee;
        if (s-beg < 1024) ee = cache[s-beg];
        else { float v = aqd + g_ah[g_adj[s].x]; v = v>0.f? v:0.2f*v; ee = __expf(v-mx); }
        float a = ee*inv;
        g_alpha[s] = a;
        if (s-beg < 1024) cache[s-beg] = a;
    }
    __syncthreads();
    float acc = 0.f;
    for (int s=beg; s<end; s++){
        float a; int src;
        if (s-beg < 1024){ a = cache[s-beg]; src = scache[s-beg]; }
        else { a = g_alpha[s]; src = g_adj[s].x; }
        acc += a * h[(size_t)src*128 + t];
    }
    cx[(size_t)d*128 + t] = acc;
}

__global__ void k_le(const float* __restrict__ cx, const float* __restrict__ lw1,
                     const float* __restrict__ lw2, const float* __restrict__ lw3){
    int node = blockIdx.x*8 + (threadIdx.x>>5);
    int lane = threadIdx.x & 31;
    const float4* c4 = (const float4*)cx;
    const float4* w14 = (const float4*)lw1;
    const float4* w24 = (const float4*)lw2;
    const float4* w34 = (const float4*)lw3;
    float4 v = c4[(size_t)node*32+lane];
    float4 w1v = w14[lane], w2v = w24[lane], w3v = w34[lane];
    float s1 = v.x*w1v.x + v.y*w1v.y + v.z*w1v.z + v.w*w1v.w;
    float s2 = v.x*w2v.x + v.y*w2v.y + v.z*w2v.z + v.w*w2v.w;
    float s3 = v.x*w3v.x + v.y*w3v.y + v.z*w3v.z + v.w*w3v.w;
    #pragma unroll
    for (int o=16;o;o>>=1){
        s1 += __shfl_down_sync(0xffffffffu,s1,o);
        s2 += __shfl_down_sync(0xffffffffu,s2,o);
        s3 += __shfl_down_sync(0xffffffffu,s3,o);
    }
    if (!lane){ g_cl1[node]=s1; g_cl2[node]=s2; g_cl3[node]=s3; }
}
__global__ void k_fit(const float* __restrict__ lb1){
    int d = blockIdx.x*blockDim.x + threadIdx.x;
    if (d >= N_) return;
    int beg=g_rowptr[d], end=g_rowptr[d+1];
    float s = 0.f;
    for (int q=beg;q<end;q++) s += g_cl3[g_adj[q].x];
    float aggr = (float)(end-beg)*g_cl2[d] - s;
    float z = g_cl1[d] + lb1[0] + aggr;
    g_fit[d] = 1.f/(1.f + __expf(-z));
}

// ---------------- top-K via 4x8-bit histogram radix select ----------------
__global__ void k_topk(){
    __shared__ int hist[256];
    __shared__ int wred[8];
    __shared__ unsigned s_pref;
    __shared__ int s_need;
    int tid=threadIdx.x, lane=tid&31, wid=tid>>5;
    if (tid==0){ s_pref=0u; s_need=K_; }
    unsigned keys[32];
    #pragma unroll
    for (int q=0;q<32;q++){
        unsigned u=__float_as_uint(g_fit[tid*32+q]);
        keys[q] = (u & 0x80000000u) ? ~u : (u | 0x80000000u);
    }
    __syncthreads();
    for (int round=0; round<4; round++){
        int shift = 24 - 8*round;
        hist[tid]=0;
        __syncthreads();
        unsigned pref = s_pref;
        #pragma unroll
        for (int q=0;q<32;q++){
            unsigned k = keys[q];
            bool match = (round==0) || ((k >> (shift+8)) == (pref >> (shift+8)));
            if (match) atomicAdd(&hist[(k>>shift)&0xFFu], 1);
        }
        __syncthreads();
        int mine = hist[255-tid];
        int v = mine;
        #pragma unroll
        for (int o=1;o<32;o<<=1){ int t2=__shfl_up_sync(0xffffffffu,v,o); if(lane>=o) v+=t2; }
        if (lane==31) wred[wid]=v;
        __syncthreads();
        int woff=0;
        #pragma unroll
        for (int w=0;w<8;w++) if (w<wid) woff+=wred[w];
        v += woff;
        int need0 = s_need;
        int vex = v - mine;
        if (v >= need0 && vex < need0){
            s_pref = s_pref | ((unsigned)(255-tid) << shift);
            s_need = need0 - vex;
        }
        __syncthreads();
    }
    unsigned thr = s_pref;
    int need = s_need;
    int tcnt=0;
    #pragma unroll
    for (int q=0;q<32;q++) tcnt += (keys[q]==thr);
    int v=tcnt;
    #pragma unroll
    for (int o=1;o<32;o<<=1){ int t2=__shfl_up_sync(0xffffffffu,v,o); if(lane>=o) v+=t2; }
    if (lane==31) wred[wid]=v;
    __syncthreads();
    int woff=0;
    #pragma unroll
    for (int w=0;w<8;w++) if (w<wid) woff+=wred[w];
    int rank = v - tcnt + woff;
    int scnt=0;
    int selq[32];
    #pragma unroll
    for (int q=0;q<32;q++){
        unsigned k=keys[q];
        bool eq = (k==thr);
        int s = (k>thr) || (eq && rank < need);
        if (eq) rank++;
        selq[q]=s;
        g_sel[tid*32+q]=s;
        scnt+=s;
    }
    __syncthreads();
    v=scnt;
    #pragma unroll
    for (int o=1;o<32;o<<=1){ int t2=__shfl_up_sync(0xffffffffu,v,o); if(lane>=o) v+=t2; }
    if (lane==31) wred[wid]=v;
    __syncthreads();
    woff=0;
    #pragma unroll
    for (int w=0;w<8;w++) if (w<wid) woff+=wred[w];
    int base = v - scnt + woff;
    #pragma unroll
    for (int q=0;q<32;q++){
        int i = tid*32+q;
        if (selq[q]){ g_col[i]=base; g_ncol[base]=i; base++; }
        else g_col[i]=-1;
    }
}

__global__ void k_xp(const float* __restrict__ cx){
    int i = blockIdx.x, t = threadIdx.x;
    if (!g_sel[i]) return;
    g_xp[(size_t)g_col[i]*128 + t] = cx[(size_t)i*128 + t] * g_fit[i];
}

// ---------------- S CSR (by source): count + fill from dst rows ----------------
__global__ void k_scount(){
    int d = blockIdx.x*blockDim.x + threadIdx.x;
    if (d >= N_ || !g_sel[d]) return;
    int beg=g_rowptr[d], end=g_rowptr[d+1];
    for (int p=beg;p<end;p++) atomicAdd(&g_scnt[g_adj[p].x], 1);
}
__global__ void k_sfill(){
    int d = blockIdx.x*blockDim.x + threadIdx.x;
    if (d >= N_ || !g_sel[d]) return;
    int colk = g_col[d];
    int beg=g_rowptr[d], end=g_rowptr[d+1];
    for (int p=beg;p<end;p++){
        int s = g_adj[p].x;
        int pos = g_srowptr[s] + atomicAdd(&g_fill[s],1);
        g_sp[pos] = make_int2(colk, __float_as_int(g_alpha[p]));
    }
}

// ---------------- W = A*S (sparse rows): count, fill ----------------
__global__ void k_wcount(){
    int s = blockIdx.x*blockDim.x + threadIdx.x;
    if (s >= N_) return;
    int ob=g_orowptr[s], oe=g_orowptr[s+1];
    int total=0;
    for (int f=ob;f<oe;f++){
        int j = g_oadj[f];
        total += g_srowptr[j+1]-g_srowptr[j];
    }
    g_wcnt[s]=total;
}
// warp per source: copy S_j lists into W row
__global__ void k_wfill(){
    int s = blockIdx.x*8 + (threadIdx.x>>5);
    int lane = threadIdx.x & 31;
    int wpos = g_wrowptr[s];
    int ob=g_orowptr[s], oe=g_orowptr[s+1];
    for (int f=ob;f<oe;f++){
        int j = g_oadj[f];
        int sb=g_srowptr[j], len=g_srowptr[j+1]-sb;
        for (int q=lane;q<len;q+=32) g_W[wpos+q]=g_sp[sb+q];
        wpos += len;
    }
}

// ---------------- Ac row gather with smem accumulator (flat W rows) ----------------
__global__ void k_AcRow(){
    __shared__ __align__(16) float acc[K_];
    int k = blockIdx.x, tid = threadIdx.x;
    int lane = tid & 31, w = tid >> 5, nw = blockDim.x >> 5;
    {
        float4 z = make_float4(0,0,0,0);
        float4* a4 = (float4*)acc;
        #pragma unroll
        for (int m=0;m<4;m++) a4[tid + m*256] = z;
    }
    __syncthreads();
    int d = g_ncol[k];
    int ib = g_rowptr[d], ie = g_rowptr[d+1];
    for (int p=ib+w; p<ie; p+=nw){
        int s = g_adj[p].x;
        float ae = g_alpha[p];
        int wb = g_wrowptr[s], we = g_wrowptr[s+1];
        int q = wb + lane;
        for (; q+32 < we; q += 64){
            int2 e0 = g_W[q];
            int2 e1 = g_W[q+32];
            atomicAdd(&acc[e0.x], ae*__int_as_float(e0.y));
            atomicAdd(&acc[e1.x], ae*__int_as_float(e1.y));
        }
        if (q < we){
            int2 e0 = g_W[q];
            atomicAdd(&acc[e0.x], ae*__int_as_float(e0.y));
        }
    }
    __syncthreads();
    float4* orow = (float4*)&g_Ac[(size_t)k*K_];
    const float4* a4 = (const float4*)acc;
    #pragma unroll
    for (int m=0;m<4;m++) orow[tid + m*256] = a4[tid + m*256];
}

// ---------------- fused: build 8 P-rows (registers->smem), then adj = P S^T ----------------
// 1024 threads; Psh layout: lo half rows 0..3, hi half rows 4..7; half[16*g + 4*u + rr]
__global__ void k_adjF(float* __restrict__ adj){
    extern __shared__ __align__(16) float Psh[];
    int i0 = blockIdx.x*8, tid = threadIdx.x;
    const float4* Ac4 = (const float4*)g_Ac;
    #pragma unroll 1
    for (int r=0;r<8;r++){
        float4 a0 = make_float4(0,0,0,0);
        int qb=g_srowptr[i0+r], qe=g_srowptr[i0+r+1];
        for (int q=qb;q<qe;q++){
            int2 kp = g_sp[q];
            float a = __int_as_float(kp.y);
            float4 v0 = Ac4[(size_t)kp.x*(K_/4) + tid];
            a0.x += a*v0.x; a0.y += a*v0.y; a0.z += a*v0.z; a0.w += a*v0.w;
        }
        float* half = Psh + ((r>=4) ? 4*K_ : 0);
        int rr = r & 3;
        half[16*tid + 0 + rr] = a0.x; half[16*tid + 4 + rr] = a0.y;
        half[16*tid + 8 + rr] = a0.z; half[16*tid +12 + rr] = a0.w;
    }
    __syncthreads();
    for (int j=tid; j<N_; j+=1024){
        float b0=0,b1=0,b2=0,b3=0,b4=0,b5=0,b6=0,b7=0;
        int qb = g_srowptr[j], qe = g_srowptr[j+1];
        for (int q=qb;q<qe;q++){
            int2 kp = g_sp[q];
            float a = __int_as_float(kp.y);
            float4 p0 = *(const float4*)&Psh[4*kp.x];
            float4 p1 = *(const float4*)&Psh[4*K_ + 4*kp.x];
            b0 += a*p0.x; b1 += a*p0.y; b2 += a*p0.z; b3 += a*p0.w;
            b4 += a*p1.x; b5 += a*p1.y; b6 += a*p1.z; b7 += a*p1.w;
        }
        adj[(size_t)(i0+0)*N_ + j]=b0; adj[(size_t)(i0+1)*N_ + j]=b1;
        adj[(size_t)(i0+2)*N_ + j]=b2; adj[(size_t)(i0+3)*N_ + j]=b3;
        adj[(size_t)(i0+4)*N_ + j]=b4; adj[(size_t)(i0+5)*N_ + j]=b5;
        adj[(size_t)(i0+6)*N_ + j]=b6; adj[(size_t)(i0+7)*N_ + j]=b7;
    }
}

// x_out[i,:] = sum over S row i: alpha*xp[k,:]  (warp per row, float4)
__global__ void k_xout(float* __restrict__ out){
    int i = blockIdx.x*8 + (threadIdx.x>>5);
    int lane = threadIdx.x & 31;
    const float4* xp4 = (const float4*)g_xp;
    float4 acc = make_float4(0,0,0,0);
    int beg=g_srowptr[i], end=g_srowptr[i+1];
    for (int q=beg;q<end;q++){
        int2 kp = g_sp[q];
        float a = __int_as_float(kp.y);
        float4 v = xp4[(size_t)kp.x*32 + lane];
        acc.x += a*v.x; acc.y += a*v.y; acc.z += a*v.z; acc.w += a*v.w;
    }
    ((float4*)out)[(size_t)i*32 + lane] = acc;
}

// ---------------- host ----------------
static cudaStream_t get_s2(){
    static cudaStream_t s = 0;
    if (!s) cudaStreamCreate(&s);
    return s;
}
static cudaEvent_t get_ev(int which){
    static cudaEvent_t ev[4] = {0,0,0,0};
    if (!ev[which]) cudaEventCreateWithFlags(&ev[which], cudaEventDisableTiming);
    return ev[which];
}

extern "C" void kernel_launch(void* const* d_in, const int* in_sizes, int n_in,
                              void* d_out, int out_size){
    const float* nodes = (const float*)d_in[0];
    const int*   edges = (const int*)d_in[1];
    const int* e0 = edges;
    const int* e1 = edges + E_;
    const float* w1 = (const float*)d_in[3];  const float* b1 = (const float*)d_in[4];
    const float* w2 = (const float*)d_in[5];  const float* b2 = (const float*)d_in[6];
    const float* w3 = (const float*)d_in[7];  const float* b3 = (const float*)d_in[8];
    const float* w4 = (const float*)d_in[9];  const float* b4 = (const float*)d_in[10];
    const float* w5 = (const float*)d_in[11]; const float* b5 = (const float*)d_in[12];
    const float* wq = (const float*)d_in[13]; const float* bq = (const float*)d_in[14];
    const float* att = (const float*)d_in[15];
    const float* lw1 = (const float*)d_in[16]; const float* lb1 = (const float*)d_in[17];
    const float* lw2 = (const float*)d_in[18]; const float* lw3 = (const float*)d_in[19];

    float* out = (float*)d_out;
    float* x2out = out;
    float* adj  = out + (size_t)N_*H_;

    float *A,*B,*C,*T; int *scnt,*srowptr,*wcnt,*wrowptr,*fill;
    cudaGetSymbolAddress((void**)&A, g_bufA);
    cudaGetSymbolAddress((void**)&B, g_bufB);
    cudaGetSymbolAddress((void**)&C, g_bufC);
    cudaGetSymbolAddress((void**)&T, g_bufT);
    cudaGetSymbolAddress((void**)&scnt, g_scnt);
    cudaGetSymbolAddress((void**)&srowptr, g_srowptr);
    cudaGetSymbolAddress((void**)&wcnt, g_wcnt);
    cudaGetSymbolAddress((void**)&wrowptr, g_wrowptr);
    cudaGetSymbolAddress((void**)&fill, g_fill);

    const int TB = 256;
    const int MB = (M_ + TB - 1)/TB;
    const int NB = (N_ + TB - 1)/TB;

    cudaStream_t s2 = get_s2();
    cudaEvent_t evF0 = get_ev(0), evJ0 = get_ev(1), evF1 = get_ev(2), evJ1 = get_ev(3);

    // fork 0: first gemm (depends only on inputs) overlaps graph prep
    cudaEventRecord(evF0, 0);
    cudaStreamWaitEvent(s2, evF0, 0);
    k_gemm<<<128,256,0,s2>>>(nodes, w1, T);
    cudaEventRecord(evJ0, s2);

    // graph prep: dst-CSR + src-CSR with folded norms (main stream)
    k_init0<<<NB, TB>>>();
    k_count<<<MB, TB>>>(e0, e1);
    k_scan2<<<2,1024>>>();
    k_fill<<<MB, TB>>>(e0, e1);

    // encoder (needs gemm1 result)
    cudaStreamWaitEvent(0, evJ0, 0);
    k_aggr<<<N_/8,256>>>(T, b1, A, 1);
    k_gemm<<<128,256>>>(A, w2, T);
    k_aggr<<<N_/8,256>>>(T, b2, B, 1);       // B = h

    // pooling
    k_segmax<<<N_/8,256>>>(B, A);
    k_gemm<<<128,256>>>(A, wq, T);
    k_dots<<<N_/8,256>>>(T, B, att, bq);
    k_softcx<<<N_,128>>>(B, C);              // C = cx, writes positional g_alpha
    k_le<<<N_/8,256>>>(C, lw1, lw2, lw3);
    k_fit<<<NB, TB>>>(lb1);
    k_topk<<<1,256>>>();
    k_xp<<<N_,128>>>(C);

    // S CSR (by source)
    k_scount<<<NB, TB>>>();
    k_scan8192<<<1,1024>>>(scnt, srowptr);
    k_zeroN<<<NB, TB>>>(fill);
    k_sfill<<<NB, TB>>>();

    // fork 1: decoder branch (s2) overlaps W-build + AcRow + adjF (main)
    cudaEventRecord(evF1, 0);
    cudaStreamWaitEvent(s2, evF1, 0);
    k_xout<<<N_/8,256,0,s2>>>(A);            // A = x_out
    k_gemm<<<128,256,0,s2>>>(A, w3, T);
    k_aggr<<<N_/8,256,0,s2>>>(T, b3, B, 1);
    k_gemm<<<128,256,0,s2>>>(B, w4, T);
    k_aggr<<<N_/8,256,0,s2>>>(T, b4, A, 1);
    k_gemm<<<128,256,0,s2>>>(A, w5, T);
    k_aggr<<<N_/8,256,0,s2>>>(T, b5, x2out, 0);
    cudaEventRecord(evJ1, s2);

    // main: W = A*S sparse rows, Ac, adj
    k_wcount<<<NB, TB>>>();
    k_scan8192<<<1,1024>>>(wcnt, wrowptr);
    k_wfill<<<N_/8, 256>>>();
    k_AcRow<<<K_, 256>>>();
    cudaFuncSetAttribute(k_adjF, cudaFuncAttributeMaxDynamicSharedMemorySize, PSH_WORDS*4);
    k_adjF<<<N_/8, 1024, PSH_WORDS*4>>>(adj);

    // join decoder branch
    cudaStreamWaitEvent(0, evJ1, 0);
}